// round 1
// baseline (speedup 1.0000x reference)
#include <cuda_runtime.h>
#include <cuda_fp16.h>
#include <math.h>

// Problem constants
#define BATCH 8
#define SEQ   1024
#define DIM   2048      // model dim = H*HD
#define HEADS 16
#define HD    128
#define MROWS (BATCH*SEQ)   // 8192

// ---------------- scratch (device globals: allocation-free) ----------------
__device__ float g_Q[MROWS * DIM];
__device__ float g_K[MROWS * DIM];
__device__ float g_V[MROWS * DIM];
__device__ float g_CTX[MROWS * DIM];

// ---------------- helpers ----------------
__device__ __forceinline__ unsigned ld_u32(const __half* p) {
    return *reinterpret_cast<const unsigned*>(p);
}
__device__ __forceinline__ unsigned pack_h2(__half a, __half b) {
    __half2 h = __halves2half2(a, b);   // a -> low 16 bits (element with lower index)
    return *reinterpret_cast<unsigned*>(&h);
}
__device__ __forceinline__ void split_f32(float x, __half& hi, __half& lo) {
    hi = __float2half_rn(x);
    lo = __float2half_rn(x - __half2float(hi));
}
// D += A(16x16 f16) * B(16x8 f16), fp32 accum
__device__ __forceinline__ void mma16816(float* c,
    unsigned a0, unsigned a1, unsigned a2, unsigned a3,
    unsigned b0, unsigned b1)
{
    asm volatile(
        "mma.sync.aligned.m16n8k16.row.col.f32.f16.f16.f32 "
        "{%0,%1,%2,%3}, {%4,%5,%6,%7}, {%8,%9}, {%0,%1,%2,%3};\n"
        : "+f"(c[0]), "+f"(c[1]), "+f"(c[2]), "+f"(c[3])
        : "r"(a0), "r"(a1), "r"(a2), "r"(a3), "r"(b0), "r"(b1));
}

// =====================================================================
// Split-precision f16 GEMM:  C[M,N] = alpha * A[M,K] @ B[K,N]   (fp32 in/out)
// C = Ah*Bh + Ah*Bl + Al*Bh  (error ~2^-21 if denormals honored, <=2.8e-4/stage worst case)
// Block tile 128x128, K-tile 32, 256 threads (8 warps, 4x2 warp grid, warp = 32x64)
// =====================================================================
#define BM 128
#define BN 128
#define BK 32
#define LDA 40   // halves; bank stride 20 words == 4 mod 32 -> conflict-free frags
#define LDB 40

__global__ __launch_bounds__(256) void gemm_split_kernel(
    const float* __restrict__ A, const float* __restrict__ B,
    float* __restrict__ C, int M, int N, int K, float alpha)
{
    __shared__ __half Ah[BM * LDA];
    __shared__ __half Al[BM * LDA];
    __shared__ __half Bh[BN * LDB];
    __shared__ __half Bl[BN * LDB];

    const int t    = threadIdx.x;
    const int lane = t & 31;
    const int wid  = t >> 5;
    const int wm   = wid >> 1;     // 0..3
    const int wn   = wid & 1;      // 0..1
    const int g    = lane >> 2;    // 0..7
    const int tig  = lane & 3;     // 0..3

    const int bm = blockIdx.y * BM;
    const int bn = blockIdx.x * BN;

    float acc[2][8][4];
#pragma unroll
    for (int i = 0; i < 2; i++)
#pragma unroll
        for (int j = 0; j < 8; j++)
#pragma unroll
            for (int r = 0; r < 4; r++) acc[i][j][r] = 0.0f;

    for (int kt = 0; kt < K; kt += BK) {
        // ---- stage global -> registers ----
        float4 ard[4], brd[4];
#pragma unroll
        for (int i = 0; i < 4; i++) {
            int f4 = t + i * 256;
            int arow = f4 >> 3, acol = (f4 & 7) * 4;          // A tile 128x32
            ard[i] = *reinterpret_cast<const float4*>(&A[(size_t)(bm + arow) * K + kt + acol]);
            int brow = f4 >> 5, bcol = (f4 & 31) * 4;         // B tile 32x128
            brd[i] = *reinterpret_cast<const float4*>(&B[(size_t)(kt + brow) * N + bn + bcol]);
        }
        __syncthreads();   // previous iteration's consumers done
        // ---- split-convert + store to smem ----
#pragma unroll
        for (int i = 0; i < 4; i++) {
            int f4 = t + i * 256;
            int arow = f4 >> 3, acol = (f4 & 7) * 4;
            const float av[4] = {ard[i].x, ard[i].y, ard[i].z, ard[i].w};
#pragma unroll
            for (int j = 0; j < 4; j++) {
                __half h, l; split_f32(av[j], h, l);
                Ah[arow * LDA + acol + j] = h;
                Al[arow * LDA + acol + j] = l;
            }
            int brow = f4 >> 5, bcol = (f4 & 31) * 4;
            const float bv[4] = {brd[i].x, brd[i].y, brd[i].z, brd[i].w};
#pragma unroll
            for (int j = 0; j < 4; j++) {
                __half h, l; split_f32(bv[j], h, l);
                Bh[(bcol + j) * LDB + brow] = h;   // transposed: [n][k]
                Bl[(bcol + j) * LDB + brow] = l;
            }
        }
        __syncthreads();
        // ---- compute ----
#pragma unroll
        for (int ks = 0; ks < BK; ks += 16) {
            unsigned ah[2][4], al_[2][4];
#pragma unroll
            for (int mf = 0; mf < 2; mf++) {
                const __half* p = &Ah[(wm * 32 + mf * 16 + g) * LDA + ks + 2 * tig];
                ah[mf][0] = ld_u32(p);
                ah[mf][1] = ld_u32(p + 8 * LDA);
                ah[mf][2] = ld_u32(p + 8);
                ah[mf][3] = ld_u32(p + 8 * LDA + 8);
                const __half* q = &Al[(wm * 32 + mf * 16 + g) * LDA + ks + 2 * tig];
                al_[mf][0] = ld_u32(q);
                al_[mf][1] = ld_u32(q + 8 * LDA);
                al_[mf][2] = ld_u32(q + 8);
                al_[mf][3] = ld_u32(q + 8 * LDA + 8);
            }
#pragma unroll
            for (int nf = 0; nf < 8; nf++) {
                const __half* pb = &Bh[(wn * 64 + nf * 8 + g) * LDB + ks + 2 * tig];
                unsigned bh0 = ld_u32(pb), bh1 = ld_u32(pb + 8);
                const __half* pl = &Bl[(wn * 64 + nf * 8 + g) * LDB + ks + 2 * tig];
                unsigned bl0 = ld_u32(pl), bl1 = ld_u32(pl + 8);
#pragma unroll
                for (int mf = 0; mf < 2; mf++) {
                    mma16816(acc[mf][nf], ah[mf][0], ah[mf][1], ah[mf][2], ah[mf][3], bh0, bh1);
                    mma16816(acc[mf][nf], ah[mf][0], ah[mf][1], ah[mf][2], ah[mf][3], bl0, bl1);
                    mma16816(acc[mf][nf], al_[mf][0], al_[mf][1], al_[mf][2], al_[mf][3], bh0, bh1);
                }
            }
        }
        __syncthreads();
    }
    // ---- epilogue ----
#pragma unroll
    for (int mf = 0; mf < 2; mf++)
#pragma unroll
        for (int nf = 0; nf < 8; nf++) {
            int row = bm + wm * 32 + mf * 16 + g;
            int col = bn + wn * 64 + nf * 8 + 2 * tig;
            float2 v0 = make_float2(acc[mf][nf][0] * alpha, acc[mf][nf][1] * alpha);
            float2 v1 = make_float2(acc[mf][nf][2] * alpha, acc[mf][nf][3] * alpha);
            *reinterpret_cast<float2*>(&C[(size_t)row * N + col])       = v0;
            *reinterpret_cast<float2*>(&C[(size_t)(row + 8) * N + col]) = v1;
        }
}

// =====================================================================
// FlashAttention-2 style kernel (split f16 MMAs, fp32 softmax/accum)
// grid (SEQ/128, HEADS, BATCH), 256 threads (8 warps x 16 q-rows)
// =====================================================================
#define QT  128
#define KT  64
#define QLD 136   // halves; 68 words == 4 mod 32 -> conflict-free
#define VLD 72    // halves; 36 words == 4 mod 32

__global__ __launch_bounds__(256) void flash_kernel()
{
    extern __shared__ __half fsm[];
    __half* Qh  = fsm;
    __half* Ql  = Qh  + QT * QLD;
    __half* Kh  = Ql  + QT * QLD;
    __half* Kl  = Kh  + KT * QLD;
    __half* Vth = Kl  + KT * QLD;
    __half* Vtl = Vth + HD * VLD;

    const int t = threadIdx.x, lane = t & 31, wid = t >> 5;
    const int g = lane >> 2, tig = lane & 3;
    const int b = blockIdx.z, h = blockIdx.y, qt = blockIdx.x;

    const float* Qg = g_Q + (size_t)(b * SEQ + qt * QT) * DIM + h * HD;
    const float* Kg = g_K + (size_t)(b * SEQ) * DIM + h * HD;
    const float* Vg = g_V + (size_t)(b * SEQ) * DIM + h * HD;

    // load + split Q tile (128 x 128)
#pragma unroll
    for (int i = 0; i < 16; i++) {
        int f4 = t + i * 256;
        int r = f4 >> 5, c = (f4 & 31) * 4;
        float4 v = *reinterpret_cast<const float4*>(&Qg[(size_t)r * DIM + c]);
        const float av[4] = {v.x, v.y, v.z, v.w};
#pragma unroll
        for (int j = 0; j < 4; j++) {
            __half hh, ll; split_f32(av[j], hh, ll);
            Qh[r * QLD + c + j] = hh;
            Ql[r * QLD + c + j] = ll;
        }
    }

    float o[16][4];
#pragma unroll
    for (int i = 0; i < 16; i++)
#pragma unroll
        for (int j = 0; j < 4; j++) o[i][j] = 0.0f;
    float m0 = -1e30f, m1 = -1e30f, l0 = 0.0f, l1 = 0.0f;

    for (int kt2 = 0; kt2 < SEQ / KT; kt2++) {
        // ---- stage K,V tiles ----
        float4 krd[8], vrd[8];
#pragma unroll
        for (int i = 0; i < 8; i++) {
            int f4 = t + i * 256;
            int r = f4 >> 5, c = (f4 & 31) * 4;
            krd[i] = *reinterpret_cast<const float4*>(&Kg[(size_t)(kt2 * KT + r) * DIM + c]);
            vrd[i] = *reinterpret_cast<const float4*>(&Vg[(size_t)(kt2 * KT + r) * DIM + c]);
        }
        __syncthreads();   // (also publishes the Q tile on the first iteration)
#pragma unroll
        for (int i = 0; i < 8; i++) {
            int f4 = t + i * 256;
            int r = f4 >> 5, c = (f4 & 31) * 4;
            const float kv[4] = {krd[i].x, krd[i].y, krd[i].z, krd[i].w};
            const float vv[4] = {vrd[i].x, vrd[i].y, vrd[i].z, vrd[i].w};
#pragma unroll
            for (int j = 0; j < 4; j++) {
                __half hh, ll;
                split_f32(kv[j], hh, ll);
                Kh[r * QLD + c + j] = hh;  Kl[r * QLD + c + j] = ll;
                split_f32(vv[j], hh, ll);
                Vth[(c + j) * VLD + r] = hh;  Vtl[(c + j) * VLD + r] = ll;  // transposed [hd][kv]
            }
        }
        __syncthreads();

        // ---- S = Q @ K^T  (16 x 64 per warp, k=128) ----
        float s[8][4];
#pragma unroll
        for (int nf = 0; nf < 8; nf++)
#pragma unroll
            for (int r = 0; r < 4; r++) s[nf][r] = 0.0f;
#pragma unroll
        for (int kk = 0; kk < 8; kk++) {
            const __half* p = &Qh[(wid * 16 + g) * QLD + kk * 16 + 2 * tig];
            unsigned qh0 = ld_u32(p),            qh1 = ld_u32(p + 8 * QLD);
            unsigned qh2 = ld_u32(p + 8),        qh3 = ld_u32(p + 8 * QLD + 8);
            const __half* q = &Ql[(wid * 16 + g) * QLD + kk * 16 + 2 * tig];
            unsigned ql0 = ld_u32(q),            ql1 = ld_u32(q + 8 * QLD);
            unsigned ql2 = ld_u32(q + 8),        ql3 = ld_u32(q + 8 * QLD + 8);
#pragma unroll
            for (int nf = 0; nf < 8; nf++) {
                const __half* pk = &Kh[(nf * 8 + g) * QLD + kk * 16 + 2 * tig];
                unsigned kh0 = ld_u32(pk), kh1 = ld_u32(pk + 8);
                const __half* pl = &Kl[(nf * 8 + g) * QLD + kk * 16 + 2 * tig];
                unsigned kl0 = ld_u32(pl), kl1 = ld_u32(pl + 8);
                mma16816(s[nf], qh0, qh1, qh2, qh3, kh0, kh1);
                mma16816(s[nf], qh0, qh1, qh2, qh3, kl0, kl1);
                mma16816(s[nf], ql0, ql1, ql2, ql3, kh0, kh1);
            }
        }

        // ---- online softmax ----
        float rmax0 = -1e30f, rmax1 = -1e30f;
#pragma unroll
        for (int nf = 0; nf < 8; nf++) {
            rmax0 = fmaxf(rmax0, fmaxf(s[nf][0], s[nf][1]));
            rmax1 = fmaxf(rmax1, fmaxf(s[nf][2], s[nf][3]));
        }
        rmax0 = fmaxf(rmax0, __shfl_xor_sync(0xffffffffu, rmax0, 1));
        rmax0 = fmaxf(rmax0, __shfl_xor_sync(0xffffffffu, rmax0, 2));
        rmax1 = fmaxf(rmax1, __shfl_xor_sync(0xffffffffu, rmax1, 1));
        rmax1 = fmaxf(rmax1, __shfl_xor_sync(0xffffffffu, rmax1, 2));
        float mn0 = fmaxf(m0, rmax0), mn1 = fmaxf(m1, rmax1);
        float f0 = __expf(m0 - mn0), f1 = __expf(m1 - mn1);
        m0 = mn0; m1 = mn1;
        float rs0 = 0.0f, rs1 = 0.0f;
#pragma unroll
        for (int nf = 0; nf < 8; nf++) {
            s[nf][0] = __expf(s[nf][0] - m0);
            s[nf][1] = __expf(s[nf][1] - m0);
            s[nf][2] = __expf(s[nf][2] - m1);
            s[nf][3] = __expf(s[nf][3] - m1);
            rs0 += s[nf][0] + s[nf][1];
            rs1 += s[nf][2] + s[nf][3];
        }
        rs0 += __shfl_xor_sync(0xffffffffu, rs0, 1);
        rs0 += __shfl_xor_sync(0xffffffffu, rs0, 2);
        rs1 += __shfl_xor_sync(0xffffffffu, rs1, 1);
        rs1 += __shfl_xor_sync(0xffffffffu, rs1, 2);
        l0 = l0 * f0 + rs0;
        l1 = l1 * f1 + rs1;
#pragma unroll
        for (int nf = 0; nf < 16; nf++) {
            o[nf][0] *= f0; o[nf][1] *= f0;
            o[nf][2] *= f1; o[nf][3] *= f1;
        }

        // ---- O += P @ V  (P 16x64 in regs, V 64x128) ----
#pragma unroll
        for (int kk2 = 0; kk2 < 4; kk2++) {
            const int j0 = 2 * kk2, j1 = 2 * kk2 + 1;
            __half h00 = __float2half_rn(s[j0][0]), h01 = __float2half_rn(s[j0][1]);
            __half h10 = __float2half_rn(s[j0][2]), h11 = __float2half_rn(s[j0][3]);
            __half h20 = __float2half_rn(s[j1][0]), h21 = __float2half_rn(s[j1][1]);
            __half h30 = __float2half_rn(s[j1][2]), h31 = __float2half_rn(s[j1][3]);
            unsigned a0h = pack_h2(h00, h01), a1h = pack_h2(h10, h11);
            unsigned a2h = pack_h2(h20, h21), a3h = pack_h2(h30, h31);
            unsigned a0l = pack_h2(__float2half_rn(s[j0][0] - __half2float(h00)),
                                   __float2half_rn(s[j0][1] - __half2float(h01)));
            unsigned a1l = pack_h2(__float2half_rn(s[j0][2] - __half2float(h10)),
                                   __float2half_rn(s[j0][3] - __half2float(h11)));
            unsigned a2l = pack_h2(__float2half_rn(s[j1][0] - __half2float(h20)),
                                   __float2half_rn(s[j1][1] - __half2float(h21)));
            unsigned a3l = pack_h2(__float2half_rn(s[j1][2] - __half2float(h30)),
                                   __float2half_rn(s[j1][3] - __half2float(h31)));
#pragma unroll
            for (int nf2 = 0; nf2 < 16; nf2++) {
                const __half* pv = &Vth[(nf2 * 8 + g) * VLD + kk2 * 16 + 2 * tig];
                unsigned vh0 = ld_u32(pv), vh1 = ld_u32(pv + 8);
                const __half* pl = &Vtl[(nf2 * 8 + g) * VLD + kk2 * 16 + 2 * tig];
                unsigned vl0 = ld_u32(pl), vl1 = ld_u32(pl + 8);
                mma16816(o[nf2], a0h, a1h, a2h, a3h, vh0, vh1);
                mma16816(o[nf2], a0h, a1h, a2h, a3h, vl0, vl1);
                mma16816(o[nf2], a0l, a1l, a2l, a3l, vh0, vh1);
            }
        }
    }

    // ---- epilogue: ctx = O / l ----
    float i0 = 1.0f / l0, i1 = 1.0f / l1;
    float* Cg = g_CTX + (size_t)(b * SEQ + qt * QT) * DIM + h * HD;
#pragma unroll
    for (int nf2 = 0; nf2 < 16; nf2++) {
        int r = wid * 16 + g, c = nf2 * 8 + 2 * tig;
        float2 v0 = make_float2(o[nf2][0] * i0, o[nf2][1] * i0);
        float2 v1 = make_float2(o[nf2][2] * i1, o[nf2][3] * i1);
        *reinterpret_cast<float2*>(&Cg[(size_t)r * DIM + c])       = v0;
        *reinterpret_cast<float2*>(&Cg[(size_t)(r + 8) * DIM + c]) = v1;
    }
}

// =====================================================================
extern "C" void kernel_launch(void* const* d_in, const int* in_sizes, int n_in,
                              void* d_out, int out_size)
{
    const float* xq  = (const float*)d_in[0];   // [8,1024,2048]
    const float* xkv = (const float*)d_in[1];   // [8,1024,2048]
    const float* Wq  = (const float*)d_in[2];   // [2048,2048]
    const float* Wk  = (const float*)d_in[3];
    const float* Wv  = (const float*)d_in[4];
    const float* Wo  = (const float*)d_in[5];
    float* out = (float*)d_out;                 // [8,1024,2048]

    float *qp, *kp, *vp, *cp;
    cudaGetSymbolAddress((void**)&qp, g_Q);
    cudaGetSymbolAddress((void**)&kp, g_K);
    cudaGetSymbolAddress((void**)&vp, g_V);
    cudaGetSymbolAddress((void**)&cp, g_CTX);

    dim3 gg(DIM / BN, MROWS / BM);   // (16, 64)
    const float qscale = 0.08838834764831845f;  // 1/sqrt(128)

    gemm_split_kernel<<<gg, 256>>>(xq,  Wq, qp, MROWS, DIM, DIM, qscale);
    gemm_split_kernel<<<gg, 256>>>(xkv, Wk, kp, MROWS, DIM, DIM, 1.0f);
    gemm_split_kernel<<<gg, 256>>>(xkv, Wv, vp, MROWS, DIM, DIM, 1.0f);

    size_t fsmem = (size_t)(2 * QT * QLD + 2 * KT * QLD + 2 * HD * VLD) * sizeof(__half);
    cudaFuncSetAttribute(flash_kernel, cudaFuncAttributeMaxDynamicSharedMemorySize, (int)fsmem);
    flash_kernel<<<dim3(SEQ / QT, HEADS, BATCH), 256, fsmem>>>();

    gemm_split_kernel<<<gg, 256>>>(cp, Wo, out, MROWS, DIM, DIM, 1.0f);
}

// round 2
// speedup vs baseline: 1.0011x; 1.0011x over previous
#include <cuda_runtime.h>
#include <cuda_fp16.h>
#include <math.h>

// Problem constants
#define BATCH 8
#define SEQ   1024
#define DIM   2048      // model dim = H*HD
#define HEADS 16
#define HD    128
#define MROWS (BATCH*SEQ)   // 8192

// ---------------- scratch (device globals: allocation-free) ----------------
__device__ float g_Q[MROWS * DIM];
__device__ float g_K[MROWS * DIM];
__device__ float g_V[MROWS * DIM];
__device__ float g_CTX[MROWS * DIM];

// ---------------- helpers ----------------
__device__ __forceinline__ unsigned ld_u32(const __half* p) {
    return *reinterpret_cast<const unsigned*>(p);
}
__device__ __forceinline__ unsigned pack_h2(__half a, __half b) {
    __half2 h = __halves2half2(a, b);   // a -> low 16 bits (element with lower index)
    return *reinterpret_cast<unsigned*>(&h);
}
__device__ __forceinline__ void split_f32(float x, __half& hi, __half& lo) {
    hi = __float2half_rn(x);
    lo = __float2half_rn(x - __half2float(hi));
}
// D += A(16x16 f16) * B(16x8 f16), fp32 accum
__device__ __forceinline__ void mma16816(float* c,
    unsigned a0, unsigned a1, unsigned a2, unsigned a3,
    unsigned b0, unsigned b1)
{
    asm volatile(
        "mma.sync.aligned.m16n8k16.row.col.f32.f16.f16.f32 "
        "{%0,%1,%2,%3}, {%4,%5,%6,%7}, {%8,%9}, {%0,%1,%2,%3};\n"
        : "+f"(c[0]), "+f"(c[1]), "+f"(c[2]), "+f"(c[3])
        : "r"(a0), "r"(a1), "r"(a2), "r"(a3), "r"(b0), "r"(b1));
}

// =====================================================================
// Split-precision f16 GEMM:  C[M,N] = alpha * A[M,K] @ B[K,N]   (fp32 in/out)
// C = Ah*Bh + Ah*Bl + Al*Bh  (error ~2^-21 if denormals honored, <=2.8e-4/stage worst case)
// Block tile 128x128, K-tile 32, 256 threads (8 warps, 4x2 warp grid, warp = 32x64)
// =====================================================================
#define BM 128
#define BN 128
#define BK 32
#define LDA 40   // halves; bank stride 20 words == 4 mod 32 -> conflict-free frags
#define LDB 40

__global__ __launch_bounds__(256) void gemm_split_kernel(
    const float* __restrict__ A, const float* __restrict__ B,
    float* __restrict__ C, int M, int N, int K, float alpha)
{
    __shared__ __half Ah[BM * LDA];
    __shared__ __half Al[BM * LDA];
    __shared__ __half Bh[BN * LDB];
    __shared__ __half Bl[BN * LDB];

    const int t    = threadIdx.x;
    const int lane = t & 31;
    const int wid  = t >> 5;
    const int wm   = wid >> 1;     // 0..3
    const int wn   = wid & 1;      // 0..1
    const int g    = lane >> 2;    // 0..7
    const int tig  = lane & 3;     // 0..3

    const int bm = blockIdx.y * BM;
    const int bn = blockIdx.x * BN;

    float acc[2][8][4];
#pragma unroll
    for (int i = 0; i < 2; i++)
#pragma unroll
        for (int j = 0; j < 8; j++)
#pragma unroll
            for (int r = 0; r < 4; r++) acc[i][j][r] = 0.0f;

    for (int kt = 0; kt < K; kt += BK) {
        // ---- stage global -> registers ----
        float4 ard[4], brd[4];
#pragma unroll
        for (int i = 0; i < 4; i++) {
            int f4 = t + i * 256;
            int arow = f4 >> 3, acol = (f4 & 7) * 4;          // A tile 128x32
            ard[i] = *reinterpret_cast<const float4*>(&A[(size_t)(bm + arow) * K + kt + acol]);
            int brow = f4 >> 5, bcol = (f4 & 31) * 4;         // B tile 32x128
            brd[i] = *reinterpret_cast<const float4*>(&B[(size_t)(kt + brow) * N + bn + bcol]);
        }
        __syncthreads();   // previous iteration's consumers done
        // ---- split-convert + store to smem ----
#pragma unroll
        for (int i = 0; i < 4; i++) {
            int f4 = t + i * 256;
            int arow = f4 >> 3, acol = (f4 & 7) * 4;
            const float av[4] = {ard[i].x, ard[i].y, ard[i].z, ard[i].w};
#pragma unroll
            for (int j = 0; j < 4; j++) {
                __half h, l; split_f32(av[j], h, l);
                Ah[arow * LDA + acol + j] = h;
                Al[arow * LDA + acol + j] = l;
            }
            int brow = f4 >> 5, bcol = (f4 & 31) * 4;
            const float bv[4] = {brd[i].x, brd[i].y, brd[i].z, brd[i].w};
#pragma unroll
            for (int j = 0; j < 4; j++) {
                __half h, l; split_f32(bv[j], h, l);
                Bh[(bcol + j) * LDB + brow] = h;   // transposed: [n][k]
                Bl[(bcol + j) * LDB + brow] = l;
            }
        }
        __syncthreads();
        // ---- compute ----
#pragma unroll
        for (int ks = 0; ks < BK; ks += 16) {
            unsigned ah[2][4], al_[2][4];
#pragma unroll
            for (int mf = 0; mf < 2; mf++) {
                const __half* p = &Ah[(wm * 32 + mf * 16 + g) * LDA + ks + 2 * tig];
                ah[mf][0] = ld_u32(p);
                ah[mf][1] = ld_u32(p + 8 * LDA);
                ah[mf][2] = ld_u32(p + 8);
                ah[mf][3] = ld_u32(p + 8 * LDA + 8);
                const __half* q = &Al[(wm * 32 + mf * 16 + g) * LDA + ks + 2 * tig];
                al_[mf][0] = ld_u32(q);
                al_[mf][1] = ld_u32(q + 8 * LDA);
                al_[mf][2] = ld_u32(q + 8);
                al_[mf][3] = ld_u32(q + 8 * LDA + 8);
            }
#pragma unroll
            for (int nf = 0; nf < 8; nf++) {
                const __half* pb = &Bh[(wn * 64 + nf * 8 + g) * LDB + ks + 2 * tig];
                unsigned bh0 = ld_u32(pb), bh1 = ld_u32(pb + 8);
                const __half* pl = &Bl[(wn * 64 + nf * 8 + g) * LDB + ks + 2 * tig];
                unsigned bl0 = ld_u32(pl), bl1 = ld_u32(pl + 8);
#pragma unroll
                for (int mf = 0; mf < 2; mf++) {
                    mma16816(acc[mf][nf], ah[mf][0], ah[mf][1], ah[mf][2], ah[mf][3], bh0, bh1);
                    mma16816(acc[mf][nf], ah[mf][0], ah[mf][1], ah[mf][2], ah[mf][3], bl0, bl1);
                    mma16816(acc[mf][nf], al_[mf][0], al_[mf][1], al_[mf][2], al_[mf][3], bh0, bh1);
                }
            }
        }
        __syncthreads();
    }
    // ---- epilogue ----
#pragma unroll
    for (int mf = 0; mf < 2; mf++)
#pragma unroll
        for (int nf = 0; nf < 8; nf++) {
            int row = bm + wm * 32 + mf * 16 + g;
            int col = bn + wn * 64 + nf * 8 + 2 * tig;
            float2 v0 = make_float2(acc[mf][nf][0] * alpha, acc[mf][nf][1] * alpha);
            float2 v1 = make_float2(acc[mf][nf][2] * alpha, acc[mf][nf][3] * alpha);
            *reinterpret_cast<float2*>(&C[(size_t)row * N + col])       = v0;
            *reinterpret_cast<float2*>(&C[(size_t)(row + 8) * N + col]) = v1;
        }
}

// =====================================================================
// FlashAttention-2 style kernel (split f16 MMAs, fp32 softmax/accum)
// grid (SEQ/128, HEADS, BATCH), 256 threads (8 warps x 16 q-rows)
// =====================================================================
#define QT  128
#define KT  64
#define QLD 136   // halves; 68 words == 4 mod 32 -> conflict-free
#define VLD 72    // halves; 36 words == 4 mod 32

__global__ __launch_bounds__(256) void flash_kernel()
{
    extern __shared__ __half fsm[];
    __half* Qh  = fsm;
    __half* Ql  = Qh  + QT * QLD;
    __half* Kh  = Ql  + QT * QLD;
    __half* Kl  = Kh  + KT * QLD;
    __half* Vth = Kl  + KT * QLD;
    __half* Vtl = Vth + HD * VLD;

    const int t = threadIdx.x, lane = t & 31, wid = t >> 5;
    const int g = lane >> 2, tig = lane & 3;
    const int b = blockIdx.z, h = blockIdx.y, qt = blockIdx.x;

    const float* Qg = g_Q + (size_t)(b * SEQ + qt * QT) * DIM + h * HD;
    const float* Kg = g_K + (size_t)(b * SEQ) * DIM + h * HD;
    const float* Vg = g_V + (size_t)(b * SEQ) * DIM + h * HD;

    // load + split Q tile (128 x 128)
#pragma unroll
    for (int i = 0; i < 16; i++) {
        int f4 = t + i * 256;
        int r = f4 >> 5, c = (f4 & 31) * 4;
        float4 v = *reinterpret_cast<const float4*>(&Qg[(size_t)r * DIM + c]);
        const float av[4] = {v.x, v.y, v.z, v.w};
#pragma unroll
        for (int j = 0; j < 4; j++) {
            __half hh, ll; split_f32(av[j], hh, ll);
            Qh[r * QLD + c + j] = hh;
            Ql[r * QLD + c + j] = ll;
        }
    }

    float o[16][4];
#pragma unroll
    for (int i = 0; i < 16; i++)
#pragma unroll
        for (int j = 0; j < 4; j++) o[i][j] = 0.0f;
    float m0 = -1e30f, m1 = -1e30f, l0 = 0.0f, l1 = 0.0f;

    for (int kt2 = 0; kt2 < SEQ / KT; kt2++) {
        // ---- stage K,V tiles ----
        float4 krd[8], vrd[8];
#pragma unroll
        for (int i = 0; i < 8; i++) {
            int f4 = t + i * 256;
            int r = f4 >> 5, c = (f4 & 31) * 4;
            krd[i] = *reinterpret_cast<const float4*>(&Kg[(size_t)(kt2 * KT + r) * DIM + c]);
            vrd[i] = *reinterpret_cast<const float4*>(&Vg[(size_t)(kt2 * KT + r) * DIM + c]);
        }
        __syncthreads();   // (also publishes the Q tile on the first iteration)
#pragma unroll
        for (int i = 0; i < 8; i++) {
            int f4 = t + i * 256;
            int r = f4 >> 5, c = (f4 & 31) * 4;
            const float kv[4] = {krd[i].x, krd[i].y, krd[i].z, krd[i].w};
            const float vv[4] = {vrd[i].x, vrd[i].y, vrd[i].z, vrd[i].w};
#pragma unroll
            for (int j = 0; j < 4; j++) {
                __half hh, ll;
                split_f32(kv[j], hh, ll);
                Kh[r * QLD + c + j] = hh;  Kl[r * QLD + c + j] = ll;
                split_f32(vv[j], hh, ll);
                Vth[(c + j) * VLD + r] = hh;  Vtl[(c + j) * VLD + r] = ll;  // transposed [hd][kv]
            }
        }
        __syncthreads();

        // ---- S = Q @ K^T  (16 x 64 per warp, k=128) ----
        float s[8][4];
#pragma unroll
        for (int nf = 0; nf < 8; nf++)
#pragma unroll
            for (int r = 0; r < 4; r++) s[nf][r] = 0.0f;
#pragma unroll
        for (int kk = 0; kk < 8; kk++) {
            const __half* p = &Qh[(wid * 16 + g) * QLD + kk * 16 + 2 * tig];
            unsigned qh0 = ld_u32(p),            qh1 = ld_u32(p + 8 * QLD);
            unsigned qh2 = ld_u32(p + 8),        qh3 = ld_u32(p + 8 * QLD + 8);
            const __half* q = &Ql[(wid * 16 + g) * QLD + kk * 16 + 2 * tig];
            unsigned ql0 = ld_u32(q),            ql1 = ld_u32(q + 8 * QLD);
            unsigned ql2 = ld_u32(q + 8),        ql3 = ld_u32(q + 8 * QLD + 8);
#pragma unroll
            for (int nf = 0; nf < 8; nf++) {
                const __half* pk = &Kh[(nf * 8 + g) * QLD + kk * 16 + 2 * tig];
                unsigned kh0 = ld_u32(pk), kh1 = ld_u32(pk + 8);
                const __half* pl = &Kl[(nf * 8 + g) * QLD + kk * 16 + 2 * tig];
                unsigned kl0 = ld_u32(pl), kl1 = ld_u32(pl + 8);
                mma16816(s[nf], qh0, qh1, qh2, qh3, kh0, kh1);
                mma16816(s[nf], qh0, qh1, qh2, qh3, kl0, kl1);
                mma16816(s[nf], ql0, ql1, ql2, ql3, kh0, kh1);
            }
        }

        // ---- online softmax ----
        float rmax0 = -1e30f, rmax1 = -1e30f;
#pragma unroll
        for (int nf = 0; nf < 8; nf++) {
            rmax0 = fmaxf(rmax0, fmaxf(s[nf][0], s[nf][1]));
            rmax1 = fmaxf(rmax1, fmaxf(s[nf][2], s[nf][3]));
        }
        rmax0 = fmaxf(rmax0, __shfl_xor_sync(0xffffffffu, rmax0, 1));
        rmax0 = fmaxf(rmax0, __shfl_xor_sync(0xffffffffu, rmax0, 2));
        rmax1 = fmaxf(rmax1, __shfl_xor_sync(0xffffffffu, rmax1, 1));
        rmax1 = fmaxf(rmax1, __shfl_xor_sync(0xffffffffu, rmax1, 2));
        float mn0 = fmaxf(m0, rmax0), mn1 = fmaxf(m1, rmax1);
        float f0 = __expf(m0 - mn0), f1 = __expf(m1 - mn1);
        m0 = mn0; m1 = mn1;
        float rs0 = 0.0f, rs1 = 0.0f;
#pragma unroll
        for (int nf = 0; nf < 8; nf++) {
            s[nf][0] = __expf(s[nf][0] - m0);
            s[nf][1] = __expf(s[nf][1] - m0);
            s[nf][2] = __expf(s[nf][2] - m1);
            s[nf][3] = __expf(s[nf][3] - m1);
            rs0 += s[nf][0] + s[nf][1];
            rs1 += s[nf][2] + s[nf][3];
        }
        rs0 += __shfl_xor_sync(0xffffffffu, rs0, 1);
        rs0 += __shfl_xor_sync(0xffffffffu, rs0, 2);
        rs1 += __shfl_xor_sync(0xffffffffu, rs1, 1);
        rs1 += __shfl_xor_sync(0xffffffffu, rs1, 2);
        l0 = l0 * f0 + rs0;
        l1 = l1 * f1 + rs1;
#pragma unroll
        for (int nf = 0; nf < 16; nf++) {
            o[nf][0] *= f0; o[nf][1] *= f0;
            o[nf][2] *= f1; o[nf][3] *= f1;
        }

        // ---- O += P @ V  (P 16x64 in regs, V 64x128) ----
#pragma unroll
        for (int kk2 = 0; kk2 < 4; kk2++) {
            const int j0 = 2 * kk2, j1 = 2 * kk2 + 1;
            __half h00 = __float2half_rn(s[j0][0]), h01 = __float2half_rn(s[j0][1]);
            __half h10 = __float2half_rn(s[j0][2]), h11 = __float2half_rn(s[j0][3]);
            __half h20 = __float2half_rn(s[j1][0]), h21 = __float2half_rn(s[j1][1]);
            __half h30 = __float2half_rn(s[j1][2]), h31 = __float2half_rn(s[j1][3]);
            unsigned a0h = pack_h2(h00, h01), a1h = pack_h2(h10, h11);
            unsigned a2h = pack_h2(h20, h21), a3h = pack_h2(h30, h31);
            unsigned a0l = pack_h2(__float2half_rn(s[j0][0] - __half2float(h00)),
                                   __float2half_rn(s[j0][1] - __half2float(h01)));
            unsigned a1l = pack_h2(__float2half_rn(s[j0][2] - __half2float(h10)),
                                   __float2half_rn(s[j0][3] - __half2float(h11)));
            unsigned a2l = pack_h2(__float2half_rn(s[j1][0] - __half2float(h20)),
                                   __float2half_rn(s[j1][1] - __half2float(h21)));
            unsigned a3l = pack_h2(__float2half_rn(s[j1][2] - __half2float(h30)),
                                   __float2half_rn(s[j1][3] - __half2float(h31)));
#pragma unroll
            for (int nf2 = 0; nf2 < 16; nf2++) {
                const __half* pv = &Vth[(nf2 * 8 + g) * VLD + kk2 * 16 + 2 * tig];
                unsigned vh0 = ld_u32(pv), vh1 = ld_u32(pv + 8);
                const __half* pl = &Vtl[(nf2 * 8 + g) * VLD + kk2 * 16 + 2 * tig];
                unsigned vl0 = ld_u32(pl), vl1 = ld_u32(pl + 8);
                mma16816(o[nf2], a0h, a1h, a2h, a3h, vh0, vh1);
                mma16816(o[nf2], a0h, a1h, a2h, a3h, vl0, vl1);
                mma16816(o[nf2], a0l, a1l, a2l, a3l, vh0, vh1);
            }
        }
    }

    // ---- epilogue: ctx = O / l ----
    float i0 = 1.0f / l0, i1 = 1.0f / l1;
    float* Cg = g_CTX + (size_t)(b * SEQ + qt * QT) * DIM + h * HD;
#pragma unroll
    for (int nf2 = 0; nf2 < 16; nf2++) {
        int r = wid * 16 + g, c = nf2 * 8 + 2 * tig;
        float2 v0 = make_float2(o[nf2][0] * i0, o[nf2][1] * i0);
        float2 v1 = make_float2(o[nf2][2] * i1, o[nf2][3] * i1);
        *reinterpret_cast<float2*>(&Cg[(size_t)r * DIM + c])       = v0;
        *reinterpret_cast<float2*>(&Cg[(size_t)(r + 8) * DIM + c]) = v1;
    }
}

// =====================================================================
extern "C" void kernel_launch(void* const* d_in, const int* in_sizes, int n_in,
                              void* d_out, int out_size)
{
    const float* xq  = (const float*)d_in[0];   // [8,1024,2048]
    const float* xkv = (const float*)d_in[1];   // [8,1024,2048]
    const float* Wq  = (const float*)d_in[2];   // [2048,2048]
    const float* Wk  = (const float*)d_in[3];
    const float* Wv  = (const float*)d_in[4];
    const float* Wo  = (const float*)d_in[5];
    float* out = (float*)d_out;                 // [8,1024,2048]

    float *qp, *kp, *vp, *cp;
    cudaGetSymbolAddress((void**)&qp, g_Q);
    cudaGetSymbolAddress((void**)&kp, g_K);
    cudaGetSymbolAddress((void**)&vp, g_V);
    cudaGetSymbolAddress((void**)&cp, g_CTX);

    dim3 gg(DIM / BN, MROWS / BM);   // (16, 64)
    const float qscale = 0.08838834764831845f;  // 1/sqrt(128)

    gemm_split_kernel<<<gg, 256>>>(xq,  Wq, qp, MROWS, DIM, DIM, qscale);
    gemm_split_kernel<<<gg, 256>>>(xkv, Wk, kp, MROWS, DIM, DIM, 1.0f);
    gemm_split_kernel<<<gg, 256>>>(xkv, Wv, vp, MROWS, DIM, DIM, 1.0f);

    size_t fsmem = (size_t)(2 * QT * QLD + 2 * KT * QLD + 2 * HD * VLD) * sizeof(__half);
    cudaFuncSetAttribute(flash_kernel, cudaFuncAttributeMaxDynamicSharedMemorySize, (int)fsmem);
    flash_kernel<<<dim3(SEQ / QT, HEADS, BATCH), 256, fsmem>>>();

    gemm_split_kernel<<<gg, 256>>>(cp, Wo, out, MROWS, DIM, DIM, 1.0f);
}

// round 5
// speedup vs baseline: 2.3265x; 2.3239x over previous
#include <cuda_runtime.h>
#include <cuda_fp16.h>
#include <cstdint>
#include <math.h>

#define BATCH 8
#define SEQ   1024
#define DIM   2048
#define HEADS 16
#define HD    128
#define MROWS (BATCH*SEQ)

// ---- scratch (device globals) ----
__device__ __align__(256) float g_Q[MROWS*DIM];
__device__ __align__(256) float g_K[MROWS*DIM];
__device__ __align__(256) float g_V[MROWS*DIM];
__device__ __align__(256) float g_CTX[MROWS*DIM];
__device__ __align__(256) __half g_Xqh[MROWS*DIM], g_Xql[MROWS*DIM];
__device__ __align__(256) __half g_Xkh[MROWS*DIM], g_Xkl[MROWS*DIM];
__device__ __align__(256) __half g_Cth[MROWS*DIM], g_Ctl[MROWS*DIM];
__device__ __align__(256) __half g_Wqh[DIM*DIM], g_Wql[DIM*DIM];
__device__ __align__(256) __half g_Wkh[DIM*DIM], g_Wkl[DIM*DIM];
__device__ __align__(256) __half g_Wvh[DIM*DIM], g_Wvl[DIM*DIM];
__device__ __align__(256) __half g_Woh[DIM*DIM], g_Wol[DIM*DIM];

// ---- helpers ----
__device__ __forceinline__ unsigned ld_u32(const __half* p){ return *reinterpret_cast<const unsigned*>(p); }
__device__ __forceinline__ unsigned pack_h2(__half a, __half b){ __half2 h=__halves2half2(a,b); return *reinterpret_cast<unsigned*>(&h); }
__device__ __forceinline__ void split_f32(float x, __half& hi, __half& lo){ hi=__float2half_rn(x); lo=__float2half_rn(x-__half2float(hi)); }
__device__ __forceinline__ void mma16816(float* c, const unsigned* a, unsigned b0, unsigned b1){
    asm volatile("mma.sync.aligned.m16n8k16.row.col.f32.f16.f16.f32 {%0,%1,%2,%3},{%4,%5,%6,%7},{%8,%9},{%0,%1,%2,%3};\n"
        : "+f"(c[0]),"+f"(c[1]),"+f"(c[2]),"+f"(c[3]) : "r"(a[0]),"r"(a[1]),"r"(a[2]),"r"(a[3]),"r"(b0),"r"(b1));
}
__device__ __forceinline__ uint32_t smem_u32(const void* p){ uint32_t a; asm("{ .reg .u64 t; cvta.to.shared.u64 t, %1; cvt.u32.u64 %0, t; }":"=r"(a):"l"(p)); return a; }
__device__ __forceinline__ void cp16(uint32_t s, const void* g){ asm volatile("cp.async.cg.shared.global [%0], [%1], 16;"::"r"(s),"l"(g)); }
__device__ __forceinline__ void ldsm4(unsigned* r, uint32_t addr){
    asm volatile("ldmatrix.sync.aligned.m8n8.x4.shared.b16 {%0,%1,%2,%3}, [%4];"
        : "=r"(r[0]),"=r"(r[1]),"=r"(r[2]),"=r"(r[3]) : "r"(addr));
}

// =====================================================================
// HMMA split-f16 GEMM: C[M,2048] = alpha * A @ BT^T
// A[M,K] hi/lo fp16, BT[N,K] hi/lo fp16 (pre-split, pre-transposed).
// CTA 128x128, BK=32, 2-stage cp.async double buffer, ldmatrix frags.
// 256 threads: warp grid 4x2, warp tile 32x64.
// =====================================================================
#define GLD 40                       // halves per smem row (padded: 20r mod 32 distinct)
#define PLANE_H (128*GLD)            // 5120 halves per plane
#define STAGE_H (4*PLANE_H)          // 20480 halves per stage
#define GEMM_SMEM (2*STAGE_H*2)      // bytes: 81920

__global__ __launch_bounds__(256) void gemm_hmma(
    const __half* __restrict__ Ah_g, const __half* __restrict__ Al_g,
    const __half* __restrict__ Bh_g, const __half* __restrict__ Bl_g,
    float* __restrict__ C, float alpha)
{
    extern __shared__ __half sm[];
    const uint32_t sbase = smem_u32(sm);
    const int tid = threadIdx.x, lane = tid & 31, wid = tid >> 5;
    const int wm = wid >> 1, wn = wid & 1;
    const int g = lane >> 2, tig = lane & 3;
    const int bm = blockIdx.y * 128, bn = blockIdx.x * 128;

    // loader precompute: 8 chunks per thread (plane p = i>>1)
    const __half* gsrc[8]; uint32_t soff[8];
#pragma unroll
    for (int i = 0; i < 8; i++) {
        int p = i >> 1;
        int sub = (i & 1) * 256 + tid;       // 0..511
        int row = sub >> 2, c = sub & 3;
        const __half* base =
            (p == 0) ? Ah_g + (size_t)bm * DIM :
            (p == 1) ? Al_g + (size_t)bm * DIM :
            (p == 2) ? Bh_g + (size_t)bn * DIM :
                       Bl_g + (size_t)bn * DIM;
        gsrc[i] = base + (size_t)row * DIM + c * 8;
        soff[i] = (uint32_t)(p * PLANE_H + row * GLD + c * 8) * 2;
    }

    float acc[2][8][4];
#pragma unroll
    for (int mf = 0; mf < 2; mf++)
#pragma unroll
        for (int nf = 0; nf < 8; nf++)
#pragma unroll
            for (int r = 0; r < 4; r++) acc[mf][nf][r] = 0.0f;

    // fragment smem address bases (per-lane)
    const uint32_t a_row0 = (uint32_t)(wm * 32 + (lane & 15));
    const uint32_t a_koff = (uint32_t)((lane >> 4) * 8);
    const uint32_t b_row0 = (uint32_t)(wn * 64 + ((lane >> 3) & 1) * 8 + (lane & 7));

    // prime stage 0
    {
#pragma unroll
        for (int i = 0; i < 8; i++) cp16(sbase + soff[i], gsrc[i]);
        asm volatile("cp.async.commit_group;" ::: "memory");
    }

    for (int kt = 0; kt < DIM / 32; kt++) {
        int s = kt & 1;
        if (kt + 1 < DIM / 32) {
            uint32_t sb2 = sbase + (uint32_t)((s ^ 1) * STAGE_H) * 2;
            const int koff = (kt + 1) * 32;
#pragma unroll
            for (int i = 0; i < 8; i++) cp16(sb2 + soff[i], gsrc[i] + koff);
            asm volatile("cp.async.commit_group;" ::: "memory");
            asm volatile("cp.async.wait_group 1;" ::: "memory");
        } else {
            asm volatile("cp.async.wait_group 0;" ::: "memory");
        }
        __syncthreads();

        const uint32_t st = sbase + (uint32_t)(s * STAGE_H) * 2;
#pragma unroll
        for (int kk = 0; kk < 2; kk++) {
            unsigned ah[2][4], al[2][4];
#pragma unroll
            for (int mf = 0; mf < 2; mf++) {
                uint32_t ra = st + ((a_row0 + mf * 16) * GLD + kk * 16 + a_koff) * 2;
                ldsm4(ah[mf], ra);
                ldsm4(al[mf], ra + PLANE_H * 2);
            }
            unsigned b0h[8], b1h[8], b0l[8], b1l[8];
#pragma unroll
            for (int g2 = 0; g2 < 4; g2++) {
                uint32_t rb = st + (2 * PLANE_H + (b_row0 + g2 * 16) * GLD + kk * 16 + a_koff) * 2;
                unsigned t4[4];
                ldsm4(t4, rb);
                b0h[2*g2] = t4[0]; b0h[2*g2+1] = t4[1]; b1h[2*g2] = t4[2]; b1h[2*g2+1] = t4[3];
                ldsm4(t4, rb + PLANE_H * 2);
                b0l[2*g2] = t4[0]; b0l[2*g2+1] = t4[1]; b1l[2*g2] = t4[2]; b1l[2*g2+1] = t4[3];
            }
            // three passes: hh, hl, lh  (each acc touched once per pass -> no RAW back-to-back)
#pragma unroll
            for (int nf = 0; nf < 8; nf++) {
                mma16816(acc[0][nf], ah[0], b0h[nf], b1h[nf]);
                mma16816(acc[1][nf], ah[1], b0h[nf], b1h[nf]);
            }
#pragma unroll
            for (int nf = 0; nf < 8; nf++) {
                mma16816(acc[0][nf], ah[0], b0l[nf], b1l[nf]);
                mma16816(acc[1][nf], ah[1], b0l[nf], b1l[nf]);
            }
#pragma unroll
            for (int nf = 0; nf < 8; nf++) {
                mma16816(acc[0][nf], al[0], b0h[nf], b1h[nf]);
                mma16816(acc[1][nf], al[1], b0h[nf], b1h[nf]);
            }
        }
        __syncthreads();
    }

    // epilogue
#pragma unroll
    for (int mf = 0; mf < 2; mf++)
#pragma unroll
        for (int nf = 0; nf < 8; nf++) {
            int row = bm + wm * 32 + mf * 16 + g;
            int col = bn + wn * 64 + nf * 8 + 2 * tig;
            float2 v0 = make_float2(acc[mf][nf][0] * alpha, acc[mf][nf][1] * alpha);
            float2 v1 = make_float2(acc[mf][nf][2] * alpha, acc[mf][nf][3] * alpha);
            *reinterpret_cast<float2*>(&C[(size_t)row * DIM + col])       = v0;
            *reinterpret_cast<float2*>(&C[(size_t)(row + 8) * DIM + col]) = v1;
        }
}

// fp32 -> split fp16 (elementwise, vectorized)
__global__ __launch_bounds__(256) void split2h(const float4* __restrict__ X, __half2* __restrict__ H, __half2* __restrict__ L){
    int i = blockIdx.x * 256 + threadIdx.x;
    float4 v = X[i];
    __half hx,lx,hy,ly,hz,lz,hw,lw;
    split_f32(v.x,hx,lx); split_f32(v.y,hy,ly); split_f32(v.z,hz,lz); split_f32(v.w,hw,lw);
    H[2*i] = __halves2half2(hx,hy); H[2*i+1] = __halves2half2(hz,hw);
    L[2*i] = __halves2half2(lx,ly); L[2*i+1] = __halves2half2(lz,lw);
}

// W[K,N] fp32 -> WT[N,K] split fp16
__global__ __launch_bounds__(256) void transpose_split(const float* __restrict__ W, __half* __restrict__ TH, __half* __restrict__ TL){
    __shared__ float t[32][33];
    int x = blockIdx.x*32 + threadIdx.x, y = blockIdx.y*32 + threadIdx.y;
#pragma unroll
    for (int j = 0; j < 4; j++) t[threadIdx.y + j*8][threadIdx.x] = W[(size_t)(y + j*8)*DIM + x];
    __syncthreads();
    int x2 = blockIdx.y*32 + threadIdx.x, y2 = blockIdx.x*32 + threadIdx.y;
#pragma unroll
    for (int j = 0; j < 4; j++) {
        float v = t[threadIdx.x][threadIdx.y + j*8];
        __half h,l; split_f32(v,h,l);
        TH[(size_t)(y2 + j*8)*DIM + x2] = h;
        TL[(size_t)(y2 + j*8)*DIM + x2] = l;
    }
}

// =====================================================================
// FlashAttention-2 (unchanged passing version)
// =====================================================================
#define QT 128
#define KT 64
#define QLD 136
#define VLD 72
__global__ __launch_bounds__(256) void flash_kernel()
{
    extern __shared__ __half fsm[];
    __half* Qh = fsm;           __half* Ql = Qh + QT*QLD;
    __half* Kh = Ql + QT*QLD;   __half* Kl = Kh + KT*QLD;
    __half* Vth = Kl + KT*QLD;  __half* Vtl = Vth + HD*VLD;
    const int t = threadIdx.x, lane = t & 31, wid = t >> 5;
    const int g = lane >> 2, tig = lane & 3;
    const int b = blockIdx.z, h = blockIdx.y, qt = blockIdx.x;
    const float* Qg = g_Q + (size_t)(b*SEQ + qt*QT)*DIM + h*HD;
    const float* Kg = g_K + (size_t)(b*SEQ)*DIM + h*HD;
    const float* Vg = g_V + (size_t)(b*SEQ)*DIM + h*HD;
#pragma unroll
    for (int i = 0; i < 16; i++) {
        int f4 = t + i*256; int r = f4 >> 5, c = (f4 & 31)*4;
        float4 v = *reinterpret_cast<const float4*>(&Qg[(size_t)r*DIM + c]);
        const float av[4] = {v.x,v.y,v.z,v.w};
#pragma unroll
        for (int j = 0; j < 4; j++) { __half hh,ll; split_f32(av[j],hh,ll); Qh[r*QLD+c+j]=hh; Ql[r*QLD+c+j]=ll; }
    }
    float o[16][4];
#pragma unroll
    for (int i = 0; i < 16; i++) { o[i][0]=o[i][1]=o[i][2]=o[i][3]=0.0f; }
    float m0=-1e30f, m1=-1e30f, l0=0.0f, l1=0.0f;
    for (int kt2 = 0; kt2 < SEQ/KT; kt2++) {
        float4 krd[8], vrd[8];
#pragma unroll
        for (int i = 0; i < 8; i++) {
            int f4 = t + i*256; int r = f4 >> 5, c = (f4 & 31)*4;
            krd[i] = *reinterpret_cast<const float4*>(&Kg[(size_t)(kt2*KT + r)*DIM + c]);
            vrd[i] = *reinterpret_cast<const float4*>(&Vg[(size_t)(kt2*KT + r)*DIM + c]);
        }
        __syncthreads();
#pragma unroll
        for (int i = 0; i < 8; i++) {
            int f4 = t + i*256; int r = f4 >> 5, c = (f4 & 31)*4;
            const float kv[4] = {krd[i].x,krd[i].y,krd[i].z,krd[i].w};
            const float vv[4] = {vrd[i].x,vrd[i].y,vrd[i].z,vrd[i].w};
#pragma unroll
            for (int j = 0; j < 4; j++) {
                __half hh,ll;
                split_f32(kv[j],hh,ll); Kh[r*QLD+c+j]=hh; Kl[r*QLD+c+j]=ll;
                split_f32(vv[j],hh,ll); Vth[(c+j)*VLD+r]=hh; Vtl[(c+j)*VLD+r]=ll;
            }
        }
        __syncthreads();
        float s[8][4];
#pragma unroll
        for (int nf = 0; nf < 8; nf++) { s[nf][0]=s[nf][1]=s[nf][2]=s[nf][3]=0.0f; }
#pragma unroll
        for (int kk = 0; kk < 8; kk++) {
            const __half* p = &Qh[(wid*16+g)*QLD + kk*16 + 2*tig];
            unsigned qh[4] = {ld_u32(p), ld_u32(p+8*QLD), ld_u32(p+8), ld_u32(p+8*QLD+8)};
            const __half* q = &Ql[(wid*16+g)*QLD + kk*16 + 2*tig];
            unsigned ql[4] = {ld_u32(q), ld_u32(q+8*QLD), ld_u32(q+8), ld_u32(q+8*QLD+8)};
#pragma unroll
            for (int nf = 0; nf < 8; nf++) {
                const __half* pk = &Kh[(nf*8+g)*QLD + kk*16 + 2*tig];
                unsigned kh0=ld_u32(pk), kh1=ld_u32(pk+8);
                const __half* pl = &Kl[(nf*8+g)*QLD + kk*16 + 2*tig];
                unsigned kl0=ld_u32(pl), kl1=ld_u32(pl+8);
                mma16816(s[nf], qh, kh0, kh1);
                mma16816(s[nf], qh, kl0, kl1);
                mma16816(s[nf], ql, kh0, kh1);
            }
        }
        float r0=-1e30f, r1=-1e30f;
#pragma unroll
        for (int nf = 0; nf < 8; nf++) { r0=fmaxf(r0,fmaxf(s[nf][0],s[nf][1])); r1=fmaxf(r1,fmaxf(s[nf][2],s[nf][3])); }
        r0=fmaxf(r0,__shfl_xor_sync(~0u,r0,1)); r0=fmaxf(r0,__shfl_xor_sync(~0u,r0,2));
        r1=fmaxf(r1,__shfl_xor_sync(~0u,r1,1)); r1=fmaxf(r1,__shfl_xor_sync(~0u,r1,2));
        float mn0=fmaxf(m0,r0), mn1=fmaxf(m1,r1);
        float f0=__expf(m0-mn0), f1=__expf(m1-mn1);
        m0=mn0; m1=mn1;
        float rs0=0.0f, rs1=0.0f;
#pragma unroll
        for (int nf = 0; nf < 8; nf++) {
            s[nf][0]=__expf(s[nf][0]-m0); s[nf][1]=__expf(s[nf][1]-m0);
            s[nf][2]=__expf(s[nf][2]-m1); s[nf][3]=__expf(s[nf][3]-m1);
            rs0 += s[nf][0]+s[nf][1]; rs1 += s[nf][2]+s[nf][3];
        }
        rs0+=__shfl_xor_sync(~0u,rs0,1); rs0+=__shfl_xor_sync(~0u,rs0,2);
        rs1+=__shfl_xor_sync(~0u,rs1,1); rs1+=__shfl_xor_sync(~0u,rs1,2);
        l0 = l0*f0 + rs0; l1 = l1*f1 + rs1;
#pragma unroll
        for (int nf = 0; nf < 16; nf++) { o[nf][0]*=f0; o[nf][1]*=f0; o[nf][2]*=f1; o[nf][3]*=f1; }
#pragma unroll
        for (int kk2 = 0; kk2 < 4; kk2++) {
            const int j0 = 2*kk2, j1 = 2*kk2+1;
            __half h00=__float2half_rn(s[j0][0]), h01=__float2half_rn(s[j0][1]);
            __half h10=__float2half_rn(s[j0][2]), h11=__float2half_rn(s[j0][3]);
            __half h20=__float2half_rn(s[j1][0]), h21=__float2half_rn(s[j1][1]);
            __half h30=__float2half_rn(s[j1][2]), h31=__float2half_rn(s[j1][3]);
            unsigned ah_[4] = {pack_h2(h00,h01), pack_h2(h10,h11), pack_h2(h20,h21), pack_h2(h30,h31)};
            unsigned al_[4] = {
                pack_h2(__float2half_rn(s[j0][0]-__half2float(h00)),__float2half_rn(s[j0][1]-__half2float(h01))),
                pack_h2(__float2half_rn(s[j0][2]-__half2float(h10)),__float2half_rn(s[j0][3]-__half2float(h11))),
                pack_h2(__float2half_rn(s[j1][0]-__half2float(h20)),__float2half_rn(s[j1][1]-__half2float(h21))),
                pack_h2(__float2half_rn(s[j1][2]-__half2float(h30)),__float2half_rn(s[j1][3]-__half2float(h31)))};
#pragma unroll
            for (int nf2 = 0; nf2 < 16; nf2++) {
                const __half* pv = &Vth[(nf2*8+g)*VLD + kk2*16 + 2*tig];
                unsigned vh0=ld_u32(pv), vh1=ld_u32(pv+8);
                const __half* pl = &Vtl[(nf2*8+g)*VLD + kk2*16 + 2*tig];
                unsigned vl0=ld_u32(pl), vl1=ld_u32(pl+8);
                mma16816(o[nf2], ah_, vh0, vh1);
                mma16816(o[nf2], ah_, vl0, vl1);
                mma16816(o[nf2], al_, vh0, vh1);
            }
        }
    }
    float i0 = 1.0f/l0, i1 = 1.0f/l1;
    float* Cg = g_CTX + (size_t)(b*SEQ + qt*QT)*DIM + h*HD;
#pragma unroll
    for (int nf2 = 0; nf2 < 16; nf2++) {
        int r = wid*16 + g, c = nf2*8 + 2*tig;
        float2 v0 = make_float2(o[nf2][0]*i0, o[nf2][1]*i0);
        float2 v1 = make_float2(o[nf2][2]*i1, o[nf2][3]*i1);
        *reinterpret_cast<float2*>(&Cg[(size_t)r*DIM + c]) = v0;
        *reinterpret_cast<float2*>(&Cg[(size_t)(r+8)*DIM + c]) = v1;
    }
}

// =====================================================================
extern "C" void kernel_launch(void* const* d_in, const int* in_sizes, int n_in,
                              void* d_out, int out_size)
{
    const float* xq  = (const float*)d_in[0];
    const float* xkv = (const float*)d_in[1];
    const float* Wq  = (const float*)d_in[2];
    const float* Wk  = (const float*)d_in[3];
    const float* Wv  = (const float*)d_in[4];
    const float* Wo  = (const float*)d_in[5];
    float* out = (float*)d_out;

    float *qp, *kp, *vp, *cp;
    cudaGetSymbolAddress((void**)&qp, g_Q);
    cudaGetSymbolAddress((void**)&kp, g_K);
    cudaGetSymbolAddress((void**)&vp, g_V);
    cudaGetSymbolAddress((void**)&cp, g_CTX);
    __half *xqh,*xql,*xkh,*xkl,*cth,*ctl;
    cudaGetSymbolAddress((void**)&xqh, g_Xqh); cudaGetSymbolAddress((void**)&xql, g_Xql);
    cudaGetSymbolAddress((void**)&xkh, g_Xkh); cudaGetSymbolAddress((void**)&xkl, g_Xkl);
    cudaGetSymbolAddress((void**)&cth, g_Cth); cudaGetSymbolAddress((void**)&ctl, g_Ctl);
    __half *wqh,*wql,*wkh,*wkl,*wvh,*wvl,*woh,*wol;
    cudaGetSymbolAddress((void**)&wqh, g_Wqh); cudaGetSymbolAddress((void**)&wql, g_Wql);
    cudaGetSymbolAddress((void**)&wkh, g_Wkh); cudaGetSymbolAddress((void**)&wkl, g_Wkl);
    cudaGetSymbolAddress((void**)&wvh, g_Wvh); cudaGetSymbolAddress((void**)&wvl, g_Wvl);
    cudaGetSymbolAddress((void**)&woh, g_Woh); cudaGetSymbolAddress((void**)&wol, g_Wol);

    const float qscale = 0.08838834764831845f;  // 1/sqrt(128)
    int nb = (MROWS * DIM / 4) / 256;

    split2h<<<nb, 256>>>((const float4*)xq,  (__half2*)xqh, (__half2*)xql);
    split2h<<<nb, 256>>>((const float4*)xkv, (__half2*)xkh, (__half2*)xkl);
    dim3 tg(DIM/32, DIM/32), tb_(32, 8);
    transpose_split<<<tg, tb_>>>(Wq, wqh, wql);
    transpose_split<<<tg, tb_>>>(Wk, wkh, wkl);
    transpose_split<<<tg, tb_>>>(Wv, wvh, wvl);
    transpose_split<<<tg, tb_>>>(Wo, woh, wol);

    cudaFuncSetAttribute(gemm_hmma, cudaFuncAttributeMaxDynamicSharedMemorySize, GEMM_SMEM);
    dim3 gg(DIM/128, MROWS/128);   // (16, 64)
    gemm_hmma<<<gg, 256, GEMM_SMEM>>>(xqh, xql, wqh, wql, qp, qscale);
    gemm_hmma<<<gg, 256, GEMM_SMEM>>>(xkh, xkl, wkh, wkl, kp, 1.0f);
    gemm_hmma<<<gg, 256, GEMM_SMEM>>>(xkh, xkl, wvh, wvl, vp, 1.0f);

    size_t fsmem = (size_t)(2*QT*QLD + 2*KT*QLD + 2*HD*VLD) * sizeof(__half);
    cudaFuncSetAttribute(flash_kernel, cudaFuncAttributeMaxDynamicSharedMemorySize, (int)fsmem);
    flash_kernel<<<dim3(SEQ/QT, HEADS, BATCH), 256, fsmem>>>();

    split2h<<<nb, 256>>>((const float4*)cp, (__half2*)cth, (__half2*)ctl);
    gemm_hmma<<<gg, 256, GEMM_SMEM>>>(cth, ctl, woh, wol, out, 1.0f);
}

// round 6
// speedup vs baseline: 2.8216x; 1.2128x over previous
#include <cuda_runtime.h>
#include <cuda_fp16.h>
#include <cstdint>
#include <math.h>

#define BATCH 8
#define SEQ   1024
#define DIM   2048
#define HEADS 16
#define HD    128
#define MROWS (BATCH*SEQ)

// ---- scratch (device globals) ----
__device__ __align__(256) __half g_Qh[MROWS*DIM], g_Ql[MROWS*DIM];
__device__ __align__(256) __half g_Kh[MROWS*DIM], g_Kl[MROWS*DIM];
__device__ __align__(256) __half g_Vh[MROWS*DIM], g_Vl[MROWS*DIM];
__device__ __align__(256) __half g_Cth[MROWS*DIM], g_Ctl[MROWS*DIM];
__device__ __align__(256) __half g_Xqh[MROWS*DIM], g_Xql[MROWS*DIM];
__device__ __align__(256) __half g_Xkh[MROWS*DIM], g_Xkl[MROWS*DIM];
__device__ __align__(256) __half g_Wqh[DIM*DIM], g_Wql[DIM*DIM];
__device__ __align__(256) __half g_Wkh[DIM*DIM], g_Wkl[DIM*DIM];
__device__ __align__(256) __half g_Wvh[DIM*DIM], g_Wvl[DIM*DIM];
__device__ __align__(256) __half g_Woh[DIM*DIM], g_Wol[DIM*DIM];

// ---- helpers ----
__device__ __forceinline__ unsigned pack_h2(__half a, __half b){ __half2 h=__halves2half2(a,b); return *reinterpret_cast<unsigned*>(&h); }
__device__ __forceinline__ void split_f32(float x, __half& hi, __half& lo){ hi=__float2half_rn(x); lo=__float2half_rn(x-__half2float(hi)); }
__device__ __forceinline__ void mma16816(float* c, const unsigned* a, unsigned b0, unsigned b1){
    asm volatile("mma.sync.aligned.m16n8k16.row.col.f32.f16.f16.f32 {%0,%1,%2,%3},{%4,%5,%6,%7},{%8,%9},{%0,%1,%2,%3};\n"
        : "+f"(c[0]),"+f"(c[1]),"+f"(c[2]),"+f"(c[3]) : "r"(a[0]),"r"(a[1]),"r"(a[2]),"r"(a[3]),"r"(b0),"r"(b1));
}
__device__ __forceinline__ uint32_t smem_u32(const void* p){ uint32_t a; asm("{ .reg .u64 t; cvta.to.shared.u64 t, %1; cvt.u32.u64 %0, t; }":"=r"(a):"l"(p)); return a; }
__device__ __forceinline__ void cp16(uint32_t s, const void* g){ asm volatile("cp.async.cg.shared.global [%0], [%1], 16;"::"r"(s),"l"(g)); }
__device__ __forceinline__ void ldsm4(unsigned* r, uint32_t addr){
    asm volatile("ldmatrix.sync.aligned.m8n8.x4.shared.b16 {%0,%1,%2,%3}, [%4];"
        : "=r"(r[0]),"=r"(r[1]),"=r"(r[2]),"=r"(r[3]) : "r"(addr));
}
__device__ __forceinline__ void ldsm4t(unsigned* r, uint32_t addr){
    asm volatile("ldmatrix.sync.aligned.m8n8.x4.trans.shared.b16 {%0,%1,%2,%3}, [%4];"
        : "=r"(r[0]),"=r"(r[1]),"=r"(r[2]),"=r"(r[3]) : "r"(addr));
}
#define CP_COMMIT() asm volatile("cp.async.commit_group;" ::: "memory")
#define CP_WAIT(n)  asm volatile("cp.async.wait_group %0;" :: "n"(n) : "memory")

// =====================================================================
// HMMA split-f16 GEMM: C = alpha * A @ BT^T (A[M,K], BT[N,K] hi/lo fp16)
// CTA 128x128, BK=32, 2-stage cp.async, ldmatrix. Output: fp32 OR split fp16.
// =====================================================================
#define GLD 40
#define PLANE_H (128*GLD)
#define STAGE_H (4*PLANE_H)
#define GEMM_SMEM (2*STAGE_H*2)

__global__ __launch_bounds__(256) void gemm_hmma(
    const __half* __restrict__ Ah_g, const __half* __restrict__ Al_g,
    const __half* __restrict__ Bh_g, const __half* __restrict__ Bl_g,
    float* __restrict__ C, __half* __restrict__ Ch, __half* __restrict__ Cl,
    float alpha)
{
    extern __shared__ __half sm[];
    const uint32_t sbase = smem_u32(sm);
    const int tid = threadIdx.x, lane = tid & 31, wid = tid >> 5;
    const int wm = wid >> 1, wn = wid & 1;
    const int g = lane >> 2, tig = lane & 3;
    const int bm = blockIdx.y * 128, bn = blockIdx.x * 128;

    const __half* gsrc[8]; uint32_t soff[8];
#pragma unroll
    for (int i = 0; i < 8; i++) {
        int p = i >> 1;
        int sub = (i & 1) * 256 + tid;
        int row = sub >> 2, c = sub & 3;
        const __half* base =
            (p == 0) ? Ah_g + (size_t)bm * DIM :
            (p == 1) ? Al_g + (size_t)bm * DIM :
            (p == 2) ? Bh_g + (size_t)bn * DIM :
                       Bl_g + (size_t)bn * DIM;
        gsrc[i] = base + (size_t)row * DIM + c * 8;
        soff[i] = (uint32_t)(p * PLANE_H + row * GLD + c * 8) * 2;
    }

    float acc[2][8][4];
#pragma unroll
    for (int mf = 0; mf < 2; mf++)
#pragma unroll
        for (int nf = 0; nf < 8; nf++)
#pragma unroll
            for (int r = 0; r < 4; r++) acc[mf][nf][r] = 0.0f;

    const uint32_t a_row0 = (uint32_t)(wm * 32 + (lane & 15));
    const uint32_t a_koff = (uint32_t)((lane >> 4) * 8);
    const uint32_t b_row0 = (uint32_t)(wn * 64 + ((lane >> 3) & 1) * 8 + (lane & 7));

    {
#pragma unroll
        for (int i = 0; i < 8; i++) cp16(sbase + soff[i], gsrc[i]);
        CP_COMMIT();
    }

    for (int kt = 0; kt < DIM / 32; kt++) {
        int s = kt & 1;
        if (kt + 1 < DIM / 32) {
            uint32_t sb2 = sbase + (uint32_t)((s ^ 1) * STAGE_H) * 2;
            const int koff = (kt + 1) * 32;
#pragma unroll
            for (int i = 0; i < 8; i++) cp16(sb2 + soff[i], gsrc[i] + koff);
            CP_COMMIT();
            CP_WAIT(1);
        } else {
            CP_WAIT(0);
        }
        __syncthreads();

        const uint32_t st = sbase + (uint32_t)(s * STAGE_H) * 2;
#pragma unroll
        for (int kk = 0; kk < 2; kk++) {
            unsigned ah[2][4], al[2][4];
#pragma unroll
            for (int mf = 0; mf < 2; mf++) {
                uint32_t ra = st + ((a_row0 + mf * 16) * GLD + kk * 16 + a_koff) * 2;
                ldsm4(ah[mf], ra);
                ldsm4(al[mf], ra + PLANE_H * 2);
            }
            unsigned b0h[8], b1h[8], b0l[8], b1l[8];
#pragma unroll
            for (int g2 = 0; g2 < 4; g2++) {
                uint32_t rb = st + (2 * PLANE_H + (b_row0 + g2 * 16) * GLD + kk * 16 + a_koff) * 2;
                unsigned t4[4];
                ldsm4(t4, rb);
                b0h[2*g2] = t4[0]; b0h[2*g2+1] = t4[1]; b1h[2*g2] = t4[2]; b1h[2*g2+1] = t4[3];
                ldsm4(t4, rb + PLANE_H * 2);
                b0l[2*g2] = t4[0]; b0l[2*g2+1] = t4[1]; b1l[2*g2] = t4[2]; b1l[2*g2+1] = t4[3];
            }
#pragma unroll
            for (int nf = 0; nf < 8; nf++) {
                mma16816(acc[0][nf], ah[0], b0h[nf], b1h[nf]);
                mma16816(acc[1][nf], ah[1], b0h[nf], b1h[nf]);
            }
#pragma unroll
            for (int nf = 0; nf < 8; nf++) {
                mma16816(acc[0][nf], ah[0], b0l[nf], b1l[nf]);
                mma16816(acc[1][nf], ah[1], b0l[nf], b1l[nf]);
            }
#pragma unroll
            for (int nf = 0; nf < 8; nf++) {
                mma16816(acc[0][nf], al[0], b0h[nf], b1h[nf]);
                mma16816(acc[1][nf], al[1], b0h[nf], b1h[nf]);
            }
        }
        __syncthreads();
    }

#pragma unroll
    for (int mf = 0; mf < 2; mf++)
#pragma unroll
        for (int nf = 0; nf < 8; nf++) {
            int row = bm + wm * 32 + mf * 16 + g;
            int col = bn + wn * 64 + nf * 8 + 2 * tig;
            float v0 = acc[mf][nf][0] * alpha, v1 = acc[mf][nf][1] * alpha;
            float v2 = acc[mf][nf][2] * alpha, v3 = acc[mf][nf][3] * alpha;
            if (Ch) {
                __half h0,l0,h1,l1,h2,l2,h3,l3;
                split_f32(v0,h0,l0); split_f32(v1,h1,l1);
                split_f32(v2,h2,l2); split_f32(v3,h3,l3);
                *reinterpret_cast<__half2*>(&Ch[(size_t)row*DIM+col])     = __halves2half2(h0,h1);
                *reinterpret_cast<__half2*>(&Cl[(size_t)row*DIM+col])     = __halves2half2(l0,l1);
                *reinterpret_cast<__half2*>(&Ch[(size_t)(row+8)*DIM+col]) = __halves2half2(h2,h3);
                *reinterpret_cast<__half2*>(&Cl[(size_t)(row+8)*DIM+col]) = __halves2half2(l2,l3);
            } else {
                *reinterpret_cast<float2*>(&C[(size_t)row*DIM+col])       = make_float2(v0,v1);
                *reinterpret_cast<float2*>(&C[(size_t)(row+8)*DIM+col])   = make_float2(v2,v3);
            }
        }
}

// fp32 -> split fp16
__global__ __launch_bounds__(256) void split2h(const float4* __restrict__ X, __half2* __restrict__ H, __half2* __restrict__ L){
    int i = blockIdx.x * 256 + threadIdx.x;
    float4 v = X[i];
    __half hx,lx,hy,ly,hz,lz,hw,lw;
    split_f32(v.x,hx,lx); split_f32(v.y,hy,ly); split_f32(v.z,hz,lz); split_f32(v.w,hw,lw);
    H[2*i] = __halves2half2(hx,hy); H[2*i+1] = __halves2half2(hz,hw);
    L[2*i] = __halves2half2(lx,ly); L[2*i+1] = __halves2half2(lz,lw);
}

// W[K,N] fp32 -> WT[N,K] split fp16
__global__ __launch_bounds__(256) void transpose_split(const float* __restrict__ W, __half* __restrict__ TH, __half* __restrict__ TL){
    __shared__ float t[32][33];
    int x = blockIdx.x*32 + threadIdx.x, y = blockIdx.y*32 + threadIdx.y;
#pragma unroll
    for (int j = 0; j < 4; j++) t[threadIdx.y + j*8][threadIdx.x] = W[(size_t)(y + j*8)*DIM + x];
    __syncthreads();
    int x2 = blockIdx.y*32 + threadIdx.x, y2 = blockIdx.x*32 + threadIdx.y;
#pragma unroll
    for (int j = 0; j < 4; j++) {
        float v = t[threadIdx.x][threadIdx.y + j*8];
        __half h,l; split_f32(v,h,l);
        TH[(size_t)(y2 + j*8)*DIM + x2] = h;
        TL[(size_t)(y2 + j*8)*DIM + x2] = l;
    }
}

// =====================================================================
// flash2: FA-2 with pre-split fp16 inputs, cp.async double buffer, ldmatrix.
// grid (8, 16, 8), 256 threads (8 warps x 16 q-rows). KT=64.
// smem: 2 stages x {Kh,Kl,Vh,Vl} 16KB each = 128KB.
// Row layout: 64 rows x 256B, 16B chunk c of row r at r*256 + (c^(r&7))*16.
// S = Qh*Kh + Qh*Kl (2-term); PV 3-term.
// =====================================================================
#define FSTG 65536

__global__ __launch_bounds__(256) void flash2()
{
    extern __shared__ char fs[];
    const uint32_t sb = smem_u32(fs);
    const int tid = threadIdx.x, lane = tid & 31, wid = tid >> 5;
    const int g = lane >> 2, tig = lane & 3;
    const int b = blockIdx.z, h = blockIdx.y, qt = blockIdx.x;
    const int t8 = lane >> 3, l7 = lane & 7;

    const size_t qrow0 = (size_t)(b * SEQ + qt * 128);
    const __half* Qg = g_Qh + qrow0 * DIM + h * HD;
    const size_t kvbase = (size_t)b * SEQ * DIM + h * HD;

    // loader precompute: 16 chunks per thread per KV stage
    const __half* ksrc[16]; uint32_t kdst[16];
#pragma unroll
    for (int i = 0; i < 16; i++) {
        int p = i >> 2;
        int m = tid + 256 * (i & 3);
        int r = m >> 4, c = m & 15;
        const __half* base =
            (p == 0) ? g_Kh + kvbase : (p == 1) ? g_Kl + kvbase :
            (p == 2) ? g_Vh + kvbase : g_Vl + kvbase;
        ksrc[i] = base + (size_t)r * DIM + c * 8;
        kdst[i] = (uint32_t)(p * 16384 + r * 256 + ((c ^ (r & 7)) << 4));
    }

    // prime: Q into stage-1 area, then KV stage 0
#pragma unroll
    for (int i = 0; i < 8; i++) {
        int n = tid + 256 * i;
        int r = n >> 4, c = n & 15;
        cp16(sb + FSTG + r * 256 + ((c ^ (r & 7)) << 4), Qg + (size_t)r * DIM + c * 8);
    }
    CP_COMMIT();
#pragma unroll
    for (int i = 0; i < 16; i++) cp16(sb + kdst[i], ksrc[i]);
    CP_COMMIT();

    CP_WAIT(1);
    __syncthreads();

    // Q fragments -> registers (hi plane only; 2-term S)
    unsigned q[8][4];
#pragma unroll
    for (int kk = 0; kk < 8; kk++) {
        uint32_t row = (uint32_t)(wid * 16 + ((t8 & 1) << 3) + l7);
        uint32_t kc  = (uint32_t)(2 * kk + (t8 >> 1));
        ldsm4(q[kk], sb + FSTG + row * 256 + ((kc ^ (row & 7)) << 4));
    }
    __syncthreads();   // all warps consumed Q; stage-1 area reusable

    float o[16][4];
#pragma unroll
    for (int i = 0; i < 16; i++) { o[i][0]=o[i][1]=o[i][2]=o[i][3]=0.0f; }
    float m0 = -1e30f, m1 = -1e30f, l0 = 0.0f, l1 = 0.0f;

    for (int kt = 0; kt < SEQ / 64; kt++) {
        int s = kt & 1;
        if (kt + 1 < SEQ / 64) {
            uint32_t dst = sb + (uint32_t)((s ^ 1) * FSTG);
            size_t koff = (size_t)(kt + 1) * 64 * DIM;
#pragma unroll
            for (int i = 0; i < 16; i++) cp16(dst + kdst[i], ksrc[i] + koff);
            CP_COMMIT();
            CP_WAIT(1);
        } else {
            CP_WAIT(0);
        }
        __syncthreads();
        const uint32_t st = sb + (uint32_t)(s * FSTG);

        // ---- S = Qh*(Kh+Kl) ----
        float sc[8][4];
#pragma unroll
        for (int nf = 0; nf < 8; nf++) { sc[nf][0]=sc[nf][1]=sc[nf][2]=sc[nf][3]=0.0f; }
#pragma unroll
        for (int kk = 0; kk < 8; kk++) {
#pragma unroll
            for (int nb = 0; nb < 4; nb++) {
                uint32_t n  = (uint32_t)(nb * 16 + ((t8 >> 1) << 3) + l7);
                uint32_t kc = (uint32_t)(2 * kk + (t8 & 1));
                uint32_t ak = st + n * 256 + ((kc ^ (n & 7)) << 4);
                unsigned bh[4], bl[4];
                ldsm4(bh, ak);
                ldsm4(bl, ak + 16384);
                mma16816(sc[2*nb],   q[kk], bh[0], bh[1]);
                mma16816(sc[2*nb+1], q[kk], bh[2], bh[3]);
                mma16816(sc[2*nb],   q[kk], bl[0], bl[1]);
                mma16816(sc[2*nb+1], q[kk], bl[2], bl[3]);
            }
        }

        // ---- online softmax ----
        float r0 = -1e30f, r1 = -1e30f;
#pragma unroll
        for (int nf = 0; nf < 8; nf++) { r0 = fmaxf(r0, fmaxf(sc[nf][0], sc[nf][1])); r1 = fmaxf(r1, fmaxf(sc[nf][2], sc[nf][3])); }
        r0 = fmaxf(r0, __shfl_xor_sync(~0u, r0, 1)); r0 = fmaxf(r0, __shfl_xor_sync(~0u, r0, 2));
        r1 = fmaxf(r1, __shfl_xor_sync(~0u, r1, 1)); r1 = fmaxf(r1, __shfl_xor_sync(~0u, r1, 2));
        float mn0 = fmaxf(m0, r0), mn1 = fmaxf(m1, r1);
        float f0 = __expf(m0 - mn0), f1 = __expf(m1 - mn1);
        m0 = mn0; m1 = mn1;
        float rs0 = 0.0f, rs1 = 0.0f;
#pragma unroll
        for (int nf = 0; nf < 8; nf++) {
            sc[nf][0] = __expf(sc[nf][0] - m0); sc[nf][1] = __expf(sc[nf][1] - m0);
            sc[nf][2] = __expf(sc[nf][2] - m1); sc[nf][3] = __expf(sc[nf][3] - m1);
            rs0 += sc[nf][0] + sc[nf][1]; rs1 += sc[nf][2] + sc[nf][3];
        }
        rs0 += __shfl_xor_sync(~0u, rs0, 1); rs0 += __shfl_xor_sync(~0u, rs0, 2);
        rs1 += __shfl_xor_sync(~0u, rs1, 1); rs1 += __shfl_xor_sync(~0u, rs1, 2);
        l0 = l0 * f0 + rs0; l1 = l1 * f1 + rs1;
#pragma unroll
        for (int nf = 0; nf < 16; nf++) { o[nf][0] *= f0; o[nf][1] *= f0; o[nf][2] *= f1; o[nf][3] *= f1; }

        // ---- O += P @ V ----
#pragma unroll
        for (int kk2 = 0; kk2 < 4; kk2++) {
            const int j0 = 2*kk2, j1 = 2*kk2 + 1;
            __half h00=__float2half_rn(sc[j0][0]), h01=__float2half_rn(sc[j0][1]);
            __half h10=__float2half_rn(sc[j0][2]), h11=__float2half_rn(sc[j0][3]);
            __half h20=__float2half_rn(sc[j1][0]), h21=__float2half_rn(sc[j1][1]);
            __half h30=__float2half_rn(sc[j1][2]), h31=__float2half_rn(sc[j1][3]);
            unsigned ah_[4] = {pack_h2(h00,h01), pack_h2(h10,h11), pack_h2(h20,h21), pack_h2(h30,h31)};
            unsigned al_[4] = {
                pack_h2(__float2half_rn(sc[j0][0]-__half2float(h00)), __float2half_rn(sc[j0][1]-__half2float(h01))),
                pack_h2(__float2half_rn(sc[j0][2]-__half2float(h10)), __float2half_rn(sc[j0][3]-__half2float(h11))),
                pack_h2(__float2half_rn(sc[j1][0]-__half2float(h20)), __float2half_rn(sc[j1][1]-__half2float(h21))),
                pack_h2(__float2half_rn(sc[j1][2]-__half2float(h30)), __float2half_rn(sc[j1][3]-__half2float(h31)))};
            uint32_t kr = (uint32_t)(kk2 * 16 + ((t8 & 1) << 3) + l7);
            uint32_t vrow = st + 32768 + kr * 256;
            uint32_t sw7 = (kr & 7);
#pragma unroll
            for (int na = 0; na < 8; na++) {
                uint32_t nblk = (uint32_t)(2 * na + (t8 >> 1));
                uint32_t av = vrow + ((nblk ^ sw7) << 4);
                unsigned vh[4], vl[4];
                ldsm4t(vh, av);
                ldsm4t(vl, av + 16384);
                mma16816(o[2*na],   ah_, vh[0], vh[1]);
                mma16816(o[2*na+1], ah_, vh[2], vh[3]);
                mma16816(o[2*na],   ah_, vl[0], vl[1]);
                mma16816(o[2*na+1], ah_, vl[2], vl[3]);
                mma16816(o[2*na],   al_, vh[0], vh[1]);
                mma16816(o[2*na+1], al_, vh[2], vh[3]);
            }
        }
        __syncthreads();
    }

    // epilogue: ctx = O/l -> split fp16 planes
    float i0 = 1.0f / l0, i1 = 1.0f / l1;
    const size_t row = qrow0 + wid * 16 + g;
    __half* Ch = g_Cth + row * DIM + h * HD;
    __half* Cl = g_Ctl + row * DIM + h * HD;
#pragma unroll
    for (int nf2 = 0; nf2 < 16; nf2++) {
        int c = nf2 * 8 + 2 * tig;
        float v0 = o[nf2][0] * i0, v1 = o[nf2][1] * i0;
        float v2 = o[nf2][2] * i1, v3 = o[nf2][3] * i1;
        __half h0,l0_,h1,l1_,h2,l2_,h3,l3_;
        split_f32(v0,h0,l0_); split_f32(v1,h1,l1_);
        split_f32(v2,h2,l2_); split_f32(v3,h3,l3_);
        *reinterpret_cast<__half2*>(Ch + c)           = __halves2half2(h0,h1);
        *reinterpret_cast<__half2*>(Cl + c)           = __halves2half2(l0_,l1_);
        *reinterpret_cast<__half2*>(Ch + 8*DIM + c)   = __halves2half2(h2,h3);
        *reinterpret_cast<__half2*>(Cl + 8*DIM + c)   = __halves2half2(l2_,l3_);
    }
}

// =====================================================================
extern "C" void kernel_launch(void* const* d_in, const int* in_sizes, int n_in,
                              void* d_out, int out_size)
{
    const float* xq  = (const float*)d_in[0];
    const float* xkv = (const float*)d_in[1];
    const float* Wq  = (const float*)d_in[2];
    const float* Wk  = (const float*)d_in[3];
    const float* Wv  = (const float*)d_in[4];
    const float* Wo  = (const float*)d_in[5];
    float* out = (float*)d_out;

    __half *qh,*ql,*kh,*kl,*vh,*vl,*cth,*ctl;
    cudaGetSymbolAddress((void**)&qh, g_Qh);  cudaGetSymbolAddress((void**)&ql, g_Ql);
    cudaGetSymbolAddress((void**)&kh, g_Kh);  cudaGetSymbolAddress((void**)&kl, g_Kl);
    cudaGetSymbolAddress((void**)&vh, g_Vh);  cudaGetSymbolAddress((void**)&vl, g_Vl);
    cudaGetSymbolAddress((void**)&cth, g_Cth); cudaGetSymbolAddress((void**)&ctl, g_Ctl);
    __half *xqh,*xql,*xkh,*xkl;
    cudaGetSymbolAddress((void**)&xqh, g_Xqh); cudaGetSymbolAddress((void**)&xql, g_Xql);
    cudaGetSymbolAddress((void**)&xkh, g_Xkh); cudaGetSymbolAddress((void**)&xkl, g_Xkl);
    __half *wqh,*wql,*wkh,*wkl,*wvh,*wvl,*woh,*wol;
    cudaGetSymbolAddress((void**)&wqh, g_Wqh); cudaGetSymbolAddress((void**)&wql, g_Wql);
    cudaGetSymbolAddress((void**)&wkh, g_Wkh); cudaGetSymbolAddress((void**)&wkl, g_Wkl);
    cudaGetSymbolAddress((void**)&wvh, g_Wvh); cudaGetSymbolAddress((void**)&wvl, g_Wvl);
    cudaGetSymbolAddress((void**)&woh, g_Woh); cudaGetSymbolAddress((void**)&wol, g_Wol);

    const float qscale = 0.08838834764831845f;  // 1/sqrt(128)
    int nb = (MROWS * DIM / 4) / 256;

    split2h<<<nb, 256>>>((const float4*)xq,  (__half2*)xqh, (__half2*)xql);
    split2h<<<nb, 256>>>((const float4*)xkv, (__half2*)xkh, (__half2*)xkl);
    dim3 tg(DIM/32, DIM/32), tb_(32, 8);
    transpose_split<<<tg, tb_>>>(Wq, wqh, wql);
    transpose_split<<<tg, tb_>>>(Wk, wkh, wkl);
    transpose_split<<<tg, tb_>>>(Wv, wvh, wvl);
    transpose_split<<<tg, tb_>>>(Wo, woh, wol);

    cudaFuncSetAttribute(gemm_hmma, cudaFuncAttributeMaxDynamicSharedMemorySize, GEMM_SMEM);
    dim3 gg(DIM/128, MROWS/128);
    gemm_hmma<<<gg, 256, GEMM_SMEM>>>(xqh, xql, wqh, wql, nullptr, qh, ql, qscale);
    gemm_hmma<<<gg, 256, GEMM_SMEM>>>(xkh, xkl, wkh, wkl, nullptr, kh, kl, 1.0f);
    gemm_hmma<<<gg, 256, GEMM_SMEM>>>(xkh, xkl, wvh, wvl, nullptr, vh, vl, 1.0f);

    cudaFuncSetAttribute(flash2, cudaFuncAttributeMaxDynamicSharedMemorySize, 2 * FSTG);
    flash2<<<dim3(SEQ/128, HEADS, BATCH), 256, 2 * FSTG>>>();

    gemm_hmma<<<gg, 256, GEMM_SMEM>>>(cth, ctl, woh, wol, out, nullptr, nullptr, 1.0f);
}

// round 7
// speedup vs baseline: 3.8470x; 1.3634x over previous
#include <cuda_runtime.h>
#include <cuda_fp16.h>
#include <cstdint>
#include <math.h>

#define BATCH 8
#define SEQ   1024
#define DIM   2048
#define HEADS 16
#define HD    128
#define MROWS (BATCH*SEQ)

// ---- scratch (device globals) ----
__device__ __align__(256) __half g_Qh[MROWS*DIM];
__device__ __align__(256) __half g_Kh[MROWS*DIM], g_Kl[MROWS*DIM];
__device__ __align__(256) __half g_Vh[MROWS*DIM], g_Vl[MROWS*DIM];
__device__ __align__(256) __half g_Cth[MROWS*DIM];
__device__ __align__(256) __half g_Xqh[MROWS*DIM];
__device__ __align__(256) __half g_Xkh[MROWS*DIM];
__device__ __align__(256) __half g_Wqh[DIM*DIM], g_Wql[DIM*DIM];
__device__ __align__(256) __half g_Wkh[DIM*DIM], g_Wkl[DIM*DIM];
__device__ __align__(256) __half g_Wvh[DIM*DIM], g_Wvl[DIM*DIM];
__device__ __align__(256) __half g_Woh[DIM*DIM], g_Wol[DIM*DIM];

// ---- helpers ----
__device__ __forceinline__ unsigned pack_h2(__half a, __half b){ __half2 h=__halves2half2(a,b); return *reinterpret_cast<unsigned*>(&h); }
__device__ __forceinline__ void split_f32(float x, __half& hi, __half& lo){ hi=__float2half_rn(x); lo=__float2half_rn(x-__half2float(hi)); }
__device__ __forceinline__ void mma16816(float* c, const unsigned* a, unsigned b0, unsigned b1){
    asm volatile("mma.sync.aligned.m16n8k16.row.col.f32.f16.f16.f32 {%0,%1,%2,%3},{%4,%5,%6,%7},{%8,%9},{%0,%1,%2,%3};\n"
        : "+f"(c[0]),"+f"(c[1]),"+f"(c[2]),"+f"(c[3]) : "r"(a[0]),"r"(a[1]),"r"(a[2]),"r"(a[3]),"r"(b0),"r"(b1));
}
__device__ __forceinline__ uint32_t smem_u32(const void* p){ uint32_t a; asm("{ .reg .u64 t; cvta.to.shared.u64 t, %1; cvt.u32.u64 %0, t; }":"=r"(a):"l"(p)); return a; }
__device__ __forceinline__ void cp16(uint32_t s, const void* g){ asm volatile("cp.async.cg.shared.global [%0], [%1], 16;"::"r"(s),"l"(g)); }
__device__ __forceinline__ void ldsm4(unsigned* r, uint32_t addr){
    asm volatile("ldmatrix.sync.aligned.m8n8.x4.shared.b16 {%0,%1,%2,%3}, [%4];"
        : "=r"(r[0]),"=r"(r[1]),"=r"(r[2]),"=r"(r[3]) : "r"(addr));
}
__device__ __forceinline__ void ldsm4t(unsigned* r, uint32_t addr){
    asm volatile("ldmatrix.sync.aligned.m8n8.x4.trans.shared.b16 {%0,%1,%2,%3}, [%4];"
        : "=r"(r[0]),"=r"(r[1]),"=r"(r[2]),"=r"(r[3]) : "r"(addr));
}
#define CP_COMMIT() asm volatile("cp.async.commit_group;" ::: "memory")
#define CP_WAIT(n)  asm volatile("cp.async.wait_group %0;" :: "n"(n) : "memory")

// =====================================================================
// HMMA 2-term GEMM: C = alpha * Ah @ (Bh+Bl)^T   (A hi-plane only)
// A[M,K] fp16-hi, BT[N,K] hi/lo fp16. CTA 128x128, BK=32, 2-stage cp.async.
// 3 smem planes: A-hi, B-hi, B-lo. Output fp32 or split fp16 (Cl optional).
// =====================================================================
#define GLD 40
#define PLANE_H (128*GLD)
#define STAGE_H (3*PLANE_H)
#define GEMM_SMEM (2*STAGE_H*2)   // 61440 B

__global__ __launch_bounds__(256) void gemm_hmma(
    const __half* __restrict__ Ah_g,
    const __half* __restrict__ Bh_g, const __half* __restrict__ Bl_g,
    float* __restrict__ C, __half* __restrict__ Ch, __half* __restrict__ Cl,
    float alpha)
{
    extern __shared__ __half sm[];
    const uint32_t sbase = smem_u32(sm);
    const int tid = threadIdx.x, lane = tid & 31, wid = tid >> 5;
    const int wm = wid >> 1, wn = wid & 1;
    const int g = lane >> 2, tig = lane & 3;
    const int bm = blockIdx.y * 128, bn = blockIdx.x * 128;

    // loader: 6 chunks/thread (p = i>>1: 0=A-hi, 1=B-hi, 2=B-lo)
    const __half* gsrc[6]; uint32_t soff[6];
#pragma unroll
    for (int i = 0; i < 6; i++) {
        int p = i >> 1;
        int sub = (i & 1) * 256 + tid;
        int row = sub >> 2, c = sub & 3;
        const __half* base =
            (p == 0) ? Ah_g + (size_t)bm * DIM :
            (p == 1) ? Bh_g + (size_t)bn * DIM :
                       Bl_g + (size_t)bn * DIM;
        gsrc[i] = base + (size_t)row * DIM + c * 8;
        soff[i] = (uint32_t)(p * PLANE_H + row * GLD + c * 8) * 2;
    }

    float acc[2][8][4];
#pragma unroll
    for (int mf = 0; mf < 2; mf++)
#pragma unroll
        for (int nf = 0; nf < 8; nf++)
#pragma unroll
            for (int r = 0; r < 4; r++) acc[mf][nf][r] = 0.0f;

    const uint32_t a_row0 = (uint32_t)(wm * 32 + (lane & 15));
    const uint32_t a_koff = (uint32_t)((lane >> 4) * 8);
    const uint32_t b_row0 = (uint32_t)(wn * 64 + ((lane >> 3) & 1) * 8 + (lane & 7));

    {
#pragma unroll
        for (int i = 0; i < 6; i++) cp16(sbase + soff[i], gsrc[i]);
        CP_COMMIT();
    }

    for (int kt = 0; kt < DIM / 32; kt++) {
        int s = kt & 1;
        if (kt + 1 < DIM / 32) {
            uint32_t sb2 = sbase + (uint32_t)((s ^ 1) * STAGE_H) * 2;
            const int koff = (kt + 1) * 32;
#pragma unroll
            for (int i = 0; i < 6; i++) cp16(sb2 + soff[i], gsrc[i] + koff);
            CP_COMMIT();
            CP_WAIT(1);
        } else {
            CP_WAIT(0);
        }
        __syncthreads();

        const uint32_t st = sbase + (uint32_t)(s * STAGE_H) * 2;
#pragma unroll
        for (int kk = 0; kk < 2; kk++) {
            unsigned ah[2][4];
#pragma unroll
            for (int mf = 0; mf < 2; mf++) {
                uint32_t ra = st + ((a_row0 + mf * 16) * GLD + kk * 16 + a_koff) * 2;
                ldsm4(ah[mf], ra);
            }
            unsigned b0h[8], b1h[8], b0l[8], b1l[8];
#pragma unroll
            for (int g2 = 0; g2 < 4; g2++) {
                uint32_t rb = st + (PLANE_H + (b_row0 + g2 * 16) * GLD + kk * 16 + a_koff) * 2;
                unsigned t4[4];
                ldsm4(t4, rb);
                b0h[2*g2] = t4[0]; b0h[2*g2+1] = t4[1]; b1h[2*g2] = t4[2]; b1h[2*g2+1] = t4[3];
                ldsm4(t4, rb + PLANE_H * 2);
                b0l[2*g2] = t4[0]; b0l[2*g2+1] = t4[1]; b1l[2*g2] = t4[2]; b1l[2*g2+1] = t4[3];
            }
#pragma unroll
            for (int nf = 0; nf < 8; nf++) {
                mma16816(acc[0][nf], ah[0], b0h[nf], b1h[nf]);
                mma16816(acc[1][nf], ah[1], b0h[nf], b1h[nf]);
            }
#pragma unroll
            for (int nf = 0; nf < 8; nf++) {
                mma16816(acc[0][nf], ah[0], b0l[nf], b1l[nf]);
                mma16816(acc[1][nf], ah[1], b0l[nf], b1l[nf]);
            }
        }
        __syncthreads();
    }

#pragma unroll
    for (int mf = 0; mf < 2; mf++)
#pragma unroll
        for (int nf = 0; nf < 8; nf++) {
            int row = bm + wm * 32 + mf * 16 + g;
            int col = bn + wn * 64 + nf * 8 + 2 * tig;
            float v0 = acc[mf][nf][0] * alpha, v1 = acc[mf][nf][1] * alpha;
            float v2 = acc[mf][nf][2] * alpha, v3 = acc[mf][nf][3] * alpha;
            if (Ch) {
                __half h0,l0,h1,l1,h2,l2,h3,l3;
                split_f32(v0,h0,l0); split_f32(v1,h1,l1);
                split_f32(v2,h2,l2); split_f32(v3,h3,l3);
                *reinterpret_cast<__half2*>(&Ch[(size_t)row*DIM+col])     = __halves2half2(h0,h1);
                *reinterpret_cast<__half2*>(&Ch[(size_t)(row+8)*DIM+col]) = __halves2half2(h2,h3);
                if (Cl) {
                    *reinterpret_cast<__half2*>(&Cl[(size_t)row*DIM+col])     = __halves2half2(l0,l1);
                    *reinterpret_cast<__half2*>(&Cl[(size_t)(row+8)*DIM+col]) = __halves2half2(l2,l3);
                }
            } else {
                *reinterpret_cast<float2*>(&C[(size_t)row*DIM+col])       = make_float2(v0,v1);
                *reinterpret_cast<float2*>(&C[(size_t)(row+8)*DIM+col])   = make_float2(v2,v3);
            }
        }
}

// fp32 -> fp16 hi plane only
__global__ __launch_bounds__(256) void f32toh(const float4* __restrict__ X, __half2* __restrict__ H){
    int i = blockIdx.x * 256 + threadIdx.x;
    float4 v = X[i];
    H[2*i]   = __halves2half2(__float2half_rn(v.x), __float2half_rn(v.y));
    H[2*i+1] = __halves2half2(__float2half_rn(v.z), __float2half_rn(v.w));
}

// W[K,N] fp32 -> WT[N,K] split fp16
__global__ __launch_bounds__(256) void transpose_split(const float* __restrict__ W, __half* __restrict__ TH, __half* __restrict__ TL){
    __shared__ float t[32][33];
    int x = blockIdx.x*32 + threadIdx.x, y = blockIdx.y*32 + threadIdx.y;
#pragma unroll
    for (int j = 0; j < 4; j++) t[threadIdx.y + j*8][threadIdx.x] = W[(size_t)(y + j*8)*DIM + x];
    __syncthreads();
    int x2 = blockIdx.y*32 + threadIdx.x, y2 = blockIdx.x*32 + threadIdx.y;
#pragma unroll
    for (int j = 0; j < 4; j++) {
        float v = t[threadIdx.x][threadIdx.y + j*8];
        __half h,l; split_f32(v,h,l);
        TH[(size_t)(y2 + j*8)*DIM + x2] = h;
        TL[(size_t)(y2 + j*8)*DIM + x2] = l;
    }
}

// =====================================================================
// flash2: FA-2, pre-split fp16, cp.async double buffer, ldmatrix.
// grid (8, 16, 8), 256 threads. S = Qh*(Kh+Kl); PV 3-term. Out: Cth only.
// =====================================================================
#define FSTG 65536

__global__ __launch_bounds__(256) void flash2()
{
    extern __shared__ char fs[];
    const uint32_t sb = smem_u32(fs);
    const int tid = threadIdx.x, lane = tid & 31, wid = tid >> 5;
    const int g = lane >> 2, tig = lane & 3;
    const int b = blockIdx.z, h = blockIdx.y, qt = blockIdx.x;
    const int t8 = lane >> 3, l7 = lane & 7;

    const size_t qrow0 = (size_t)(b * SEQ + qt * 128);
    const __half* Qg = g_Qh + qrow0 * DIM + h * HD;
    const size_t kvbase = (size_t)b * SEQ * DIM + h * HD;

    const __half* ksrc[16]; uint32_t kdst[16];
#pragma unroll
    for (int i = 0; i < 16; i++) {
        int p = i >> 2;
        int m = tid + 256 * (i & 3);
        int r = m >> 4, c = m & 15;
        const __half* base =
            (p == 0) ? g_Kh + kvbase : (p == 1) ? g_Kl + kvbase :
            (p == 2) ? g_Vh + kvbase : g_Vl + kvbase;
        ksrc[i] = base + (size_t)r * DIM + c * 8;
        kdst[i] = (uint32_t)(p * 16384 + r * 256 + ((c ^ (r & 7)) << 4));
    }

#pragma unroll
    for (int i = 0; i < 8; i++) {
        int n = tid + 256 * i;
        int r = n >> 4, c = n & 15;
        cp16(sb + FSTG + r * 256 + ((c ^ (r & 7)) << 4), Qg + (size_t)r * DIM + c * 8);
    }
    CP_COMMIT();
#pragma unroll
    for (int i = 0; i < 16; i++) cp16(sb + kdst[i], ksrc[i]);
    CP_COMMIT();

    CP_WAIT(1);
    __syncthreads();

    unsigned q[8][4];
#pragma unroll
    for (int kk = 0; kk < 8; kk++) {
        uint32_t row = (uint32_t)(wid * 16 + ((t8 & 1) << 3) + l7);
        uint32_t kc  = (uint32_t)(2 * kk + (t8 >> 1));
        ldsm4(q[kk], sb + FSTG + row * 256 + ((kc ^ (row & 7)) << 4));
    }
    __syncthreads();

    float o[16][4];
#pragma unroll
    for (int i = 0; i < 16; i++) { o[i][0]=o[i][1]=o[i][2]=o[i][3]=0.0f; }
    float m0 = -1e30f, m1 = -1e30f, l0 = 0.0f, l1 = 0.0f;

    for (int kt = 0; kt < SEQ / 64; kt++) {
        int s = kt & 1;
        if (kt + 1 < SEQ / 64) {
            uint32_t dst = sb + (uint32_t)((s ^ 1) * FSTG);
            size_t koff = (size_t)(kt + 1) * 64 * DIM;
#pragma unroll
            for (int i = 0; i < 16; i++) cp16(dst + kdst[i], ksrc[i] + koff);
            CP_COMMIT();
            CP_WAIT(1);
        } else {
            CP_WAIT(0);
        }
        __syncthreads();
        const uint32_t st = sb + (uint32_t)(s * FSTG);

        float sc[8][4];
#pragma unroll
        for (int nf = 0; nf < 8; nf++) { sc[nf][0]=sc[nf][1]=sc[nf][2]=sc[nf][3]=0.0f; }
#pragma unroll
        for (int kk = 0; kk < 8; kk++) {
#pragma unroll
            for (int nb = 0; nb < 4; nb++) {
                uint32_t n  = (uint32_t)(nb * 16 + ((t8 >> 1) << 3) + l7);
                uint32_t kc = (uint32_t)(2 * kk + (t8 & 1));
                uint32_t ak = st + n * 256 + ((kc ^ (n & 7)) << 4);
                unsigned bh[4], bl[4];
                ldsm4(bh, ak);
                ldsm4(bl, ak + 16384);
                mma16816(sc[2*nb],   q[kk], bh[0], bh[1]);
                mma16816(sc[2*nb+1], q[kk], bh[2], bh[3]);
                mma16816(sc[2*nb],   q[kk], bl[0], bl[1]);
                mma16816(sc[2*nb+1], q[kk], bl[2], bl[3]);
            }
        }

        float r0 = -1e30f, r1 = -1e30f;
#pragma unroll
        for (int nf = 0; nf < 8; nf++) { r0 = fmaxf(r0, fmaxf(sc[nf][0], sc[nf][1])); r1 = fmaxf(r1, fmaxf(sc[nf][2], sc[nf][3])); }
        r0 = fmaxf(r0, __shfl_xor_sync(~0u, r0, 1)); r0 = fmaxf(r0, __shfl_xor_sync(~0u, r0, 2));
        r1 = fmaxf(r1, __shfl_xor_sync(~0u, r1, 1)); r1 = fmaxf(r1, __shfl_xor_sync(~0u, r1, 2));
        float mn0 = fmaxf(m0, r0), mn1 = fmaxf(m1, r1);
        float f0 = __expf(m0 - mn0), f1 = __expf(m1 - mn1);
        m0 = mn0; m1 = mn1;
        float rs0 = 0.0f, rs1 = 0.0f;
#pragma unroll
        for (int nf = 0; nf < 8; nf++) {
            sc[nf][0] = __expf(sc[nf][0] - m0); sc[nf][1] = __expf(sc[nf][1] - m0);
            sc[nf][2] = __expf(sc[nf][2] - m1); sc[nf][3] = __expf(sc[nf][3] - m1);
            rs0 += sc[nf][0] + sc[nf][1]; rs1 += sc[nf][2] + sc[nf][3];
        }
        rs0 += __shfl_xor_sync(~0u, rs0, 1); rs0 += __shfl_xor_sync(~0u, rs0, 2);
        rs1 += __shfl_xor_sync(~0u, rs1, 1); rs1 += __shfl_xor_sync(~0u, rs1, 2);
        l0 = l0 * f0 + rs0; l1 = l1 * f1 + rs1;
#pragma unroll
        for (int nf = 0; nf < 16; nf++) { o[nf][0] *= f0; o[nf][1] *= f0; o[nf][2] *= f1; o[nf][3] *= f1; }

#pragma unroll
        for (int kk2 = 0; kk2 < 4; kk2++) {
            const int j0 = 2*kk2, j1 = 2*kk2 + 1;
            __half h00=__float2half_rn(sc[j0][0]), h01=__float2half_rn(sc[j0][1]);
            __half h10=__float2half_rn(sc[j0][2]), h11=__float2half_rn(sc[j0][3]);
            __half h20=__float2half_rn(sc[j1][0]), h21=__float2half_rn(sc[j1][1]);
            __half h30=__float2half_rn(sc[j1][2]), h31=__float2half_rn(sc[j1][3]);
            unsigned ah_[4] = {pack_h2(h00,h01), pack_h2(h10,h11), pack_h2(h20,h21), pack_h2(h30,h31)};
            unsigned al_[4] = {
                pack_h2(__float2half_rn(sc[j0][0]-__half2float(h00)), __float2half_rn(sc[j0][1]-__half2float(h01))),
                pack_h2(__float2half_rn(sc[j0][2]-__half2float(h10)), __float2half_rn(sc[j0][3]-__half2float(h11))),
                pack_h2(__float2half_rn(sc[j1][0]-__half2float(h20)), __float2half_rn(sc[j1][1]-__half2float(h21))),
                pack_h2(__float2half_rn(sc[j1][2]-__half2float(h30)), __float2half_rn(sc[j1][3]-__half2float(h31)))};
            uint32_t kr = (uint32_t)(kk2 * 16 + ((t8 & 1) << 3) + l7);
            uint32_t vrow = st + 32768 + kr * 256;
            uint32_t sw7 = (kr & 7);
#pragma unroll
            for (int na = 0; na < 8; na++) {
                uint32_t nblk = (uint32_t)(2 * na + (t8 >> 1));
                uint32_t av = vrow + ((nblk ^ sw7) << 4);
                unsigned vh[4], vl[4];
                ldsm4t(vh, av);
                ldsm4t(vl, av + 16384);
                mma16816(o[2*na],   ah_, vh[0], vh[1]);
                mma16816(o[2*na+1], ah_, vh[2], vh[3]);
                mma16816(o[2*na],   ah_, vl[0], vl[1]);
                mma16816(o[2*na+1], ah_, vl[2], vl[3]);
                mma16816(o[2*na],   al_, vh[0], vh[1]);
                mma16816(o[2*na+1], al_, vh[2], vh[3]);
            }
        }
        __syncthreads();
    }

    // epilogue: ctx = O/l -> hi plane only (O-proj is 2-term, A hi)
    float i0 = 1.0f / l0, i1 = 1.0f / l1;
    const size_t row = qrow0 + wid * 16 + g;
    __half* Ch = g_Cth + row * DIM + h * HD;
#pragma unroll
    for (int nf2 = 0; nf2 < 16; nf2++) {
        int c = nf2 * 8 + 2 * tig;
        float v0 = o[nf2][0] * i0, v1 = o[nf2][1] * i0;
        float v2 = o[nf2][2] * i1, v3 = o[nf2][3] * i1;
        *reinterpret_cast<__half2*>(Ch + c)         = __halves2half2(__float2half_rn(v0), __float2half_rn(v1));
        *reinterpret_cast<__half2*>(Ch + 8*DIM + c) = __halves2half2(__float2half_rn(v2), __float2half_rn(v3));
    }
}

// =====================================================================
extern "C" void kernel_launch(void* const* d_in, const int* in_sizes, int n_in,
                              void* d_out, int out_size)
{
    const float* xq  = (const float*)d_in[0];
    const float* xkv = (const float*)d_in[1];
    const float* Wq  = (const float*)d_in[2];
    const float* Wk  = (const float*)d_in[3];
    const float* Wv  = (const float*)d_in[4];
    const float* Wo  = (const float*)d_in[5];
    float* out = (float*)d_out;

    __half *qh,*kh,*kl,*vh,*vl,*cth;
    cudaGetSymbolAddress((void**)&qh, g_Qh);
    cudaGetSymbolAddress((void**)&kh, g_Kh);  cudaGetSymbolAddress((void**)&kl, g_Kl);
    cudaGetSymbolAddress((void**)&vh, g_Vh);  cudaGetSymbolAddress((void**)&vl, g_Vl);
    cudaGetSymbolAddress((void**)&cth, g_Cth);
    __half *xqh,*xkh;
    cudaGetSymbolAddress((void**)&xqh, g_Xqh);
    cudaGetSymbolAddress((void**)&xkh, g_Xkh);
    __half *wqh,*wql,*wkh,*wkl,*wvh,*wvl,*woh,*wol;
    cudaGetSymbolAddress((void**)&wqh, g_Wqh); cudaGetSymbolAddress((void**)&wql, g_Wql);
    cudaGetSymbolAddress((void**)&wkh, g_Wkh); cudaGetSymbolAddress((void**)&wkl, g_Wkl);
    cudaGetSymbolAddress((void**)&wvh, g_Wvh); cudaGetSymbolAddress((void**)&wvl, g_Wvl);
    cudaGetSymbolAddress((void**)&woh, g_Woh); cudaGetSymbolAddress((void**)&wol, g_Wol);

    const float qscale = 0.08838834764831845f;  // 1/sqrt(128)
    int nb = (MROWS * DIM / 4) / 256;

    f32toh<<<nb, 256>>>((const float4*)xq,  (__half2*)xqh);
    f32toh<<<nb, 256>>>((const float4*)xkv, (__half2*)xkh);
    dim3 tg(DIM/32, DIM/32), tb_(32, 8);
    transpose_split<<<tg, tb_>>>(Wq, wqh, wql);
    transpose_split<<<tg, tb_>>>(Wk, wkh, wkl);
    transpose_split<<<tg, tb_>>>(Wv, wvh, wvl);
    transpose_split<<<tg, tb_>>>(Wo, woh, wol);

    cudaFuncSetAttribute(gemm_hmma, cudaFuncAttributeMaxDynamicSharedMemorySize, GEMM_SMEM);
    dim3 gg(DIM/128, MROWS/128);
    gemm_hmma<<<gg, 256, GEMM_SMEM>>>(xqh, wqh, wql, nullptr, qh, nullptr, qscale);
    gemm_hmma<<<gg, 256, GEMM_SMEM>>>(xkh, wkh, wkl, nullptr, kh, kl, 1.0f);
    gemm_hmma<<<gg, 256, GEMM_SMEM>>>(xkh, wvh, wvl, nullptr, vh, vl, 1.0f);

    cudaFuncSetAttribute(flash2, cudaFuncAttributeMaxDynamicSharedMemorySize, 2 * FSTG);
    flash2<<<dim3(SEQ/128, HEADS, BATCH), 256, 2 * FSTG>>>();

    gemm_hmma<<<gg, 256, GEMM_SMEM>>>(cth, woh, wol, out, nullptr, nullptr, 1.0f);
}